// round 12
// baseline (speedup 1.0000x reference)
#include <cuda_runtime.h>

#define B_    4096
#define NNODE 64
#define FIN   67
#define C1    64
#define C2    32
#define DFP   2048
#define H1D   400
#define H2D   64
#define NEDGE 512

// ---------------- scratch (device globals; no allocations allowed) ----------------
__device__ float g_P [NNODE * NNODE];            // propagation matrix P[d][s]
__device__ float g_Y1[B_ * NNODE * C1];          // X @ W1^T
__device__ float g_G1[B_ * NNODE * C1];          // P @ Y1 + b1 (pre-BN)
__device__ float g_Z2[B_ * NNODE * C2];          // relu(bn(G1)) @ W2^T
__device__ float g_G2[B_ * NNODE * C2];          // P @ Z2 + b2 (pre-BN)
__device__ float g_pool[B_ * C2];
__device__ float g_H1[B_ * H1D];
__device__ float g_H2[B_ * H2D];
__device__ float g_sum1[NNODE], g_ssq1[NNODE], g_sum2[NNODE], g_ssq2[NNODE];

// ---------------- K0: build P from edge list, zero stats ----------------
__global__ void k_prep(const int* __restrict__ el) {
    __shared__ float deg[NNODE];
    __shared__ float dinv[NNODE];
    __shared__ float Ps[NNODE * NNODE];
    int t = threadIdx.x;
    if (t < NNODE) deg[t] = 0.f;
    for (int i = t; i < NNODE * NNODE; i += 256) Ps[i] = 0.f;
    __syncthreads();
    for (int i = t; i < NEDGE + NNODE; i += 256) {
        int d = (i < NEDGE) ? el[NEDGE + i] : (i - NEDGE);
        atomicAdd(&deg[d], 1.f);
    }
    __syncthreads();
    if (t < NNODE) dinv[t] = (deg[t] > 0.f) ? rsqrtf(deg[t]) : 0.f;
    __syncthreads();
    for (int i = t; i < NEDGE + NNODE; i += 256) {
        int s = (i < NEDGE) ? el[i] : (i - NEDGE);
        int d = (i < NEDGE) ? el[NEDGE + i] : (i - NEDGE);
        atomicAdd(&Ps[d * NNODE + s], dinv[s] * dinv[d]);
    }
    __syncthreads();
    for (int i = t; i < NNODE * NNODE; i += 256) g_P[i] = Ps[i];
    if (t < NNODE) { g_sum1[t] = 0.f; g_ssq1[t] = 0.f; g_sum2[t] = 0.f; g_ssq2[t] = 0.f; }
}

// ---------------- K1: Y1 = X @ W1^T  (M=262144, K=67, N=64) ----------------
__global__ void k_gemm1(const float* __restrict__ X, const float* __restrict__ W1) {
    __shared__ __align__(16) float As[FIN * 68];   // As[k][m], m padded to 68
    __shared__ __align__(16) float Ws[FIN * 68];   // Ws[k][n]
    int t = threadIdx.x;
    int m0 = blockIdx.x * 64;
    const float* Xt = X + (size_t)m0 * FIN;
    for (int i = t; i < 64 * FIN; i += 256) {
        int r = i / FIN, k = i - r * FIN;
        As[k * 68 + r] = Xt[i];
    }
    for (int i = t; i < 64 * FIN; i += 256) {
        int n = i / FIN, k = i - n * FIN;
        Ws[k * 68 + n] = W1[i];
    }
    __syncthreads();
    int tm = (t >> 4) * 4, tn = (t & 15) * 4;
    float acc[4][4] = {};
    for (int k = 0; k < FIN; k++) {
        float4 a = *reinterpret_cast<const float4*>(&As[k * 68 + tm]);
        float4 b = *reinterpret_cast<const float4*>(&Ws[k * 68 + tn]);
        acc[0][0] = fmaf(a.x, b.x, acc[0][0]); acc[0][1] = fmaf(a.x, b.y, acc[0][1]);
        acc[0][2] = fmaf(a.x, b.z, acc[0][2]); acc[0][3] = fmaf(a.x, b.w, acc[0][3]);
        acc[1][0] = fmaf(a.y, b.x, acc[1][0]); acc[1][1] = fmaf(a.y, b.y, acc[1][1]);
        acc[1][2] = fmaf(a.y, b.z, acc[1][2]); acc[1][3] = fmaf(a.y, b.w, acc[1][3]);
        acc[2][0] = fmaf(a.z, b.x, acc[2][0]); acc[2][1] = fmaf(a.z, b.y, acc[2][1]);
        acc[2][2] = fmaf(a.z, b.z, acc[2][2]); acc[2][3] = fmaf(a.z, b.w, acc[2][3]);
        acc[3][0] = fmaf(a.w, b.x, acc[3][0]); acc[3][1] = fmaf(a.w, b.y, acc[3][1]);
        acc[3][2] = fmaf(a.w, b.z, acc[3][2]); acc[3][3] = fmaf(a.w, b.w, acc[3][3]);
    }
    #pragma unroll
    for (int i = 0; i < 4; i++) {
        float4 v = make_float4(acc[i][0], acc[i][1], acc[i][2], acc[i][3]);
        *reinterpret_cast<float4*>(&g_Y1[(size_t)(m0 + tm + i) * 64 + tn]) = v;
    }
}

// ---------------- K2: G1[b] = P @ Y1[b] + b1, with BN1 stats epilogue ----------------
__global__ void k_pgemm1(const float* __restrict__ b1) {
    __shared__ __align__(16) float Ps[4096];
    __shared__ __align__(16) float Ys[4096];
    int b = blockIdx.x, t = threadIdx.x;
    const float* src = g_Y1 + (size_t)b * 4096;
    for (int i = t; i < 4096; i += 256) { Ps[i] = g_P[i]; Ys[i] = src[i]; }
    __syncthreads();
    int d0 = (t >> 4) * 4, o0 = (t & 15) * 4;
    float acc[4][4] = {};
    #pragma unroll 4
    for (int s = 0; s < 64; s++) {
        float4 y = *reinterpret_cast<const float4*>(&Ys[s * 64 + o0]);
        #pragma unroll
        for (int i = 0; i < 4; i++) {
            float p = Ps[(d0 + i) * 64 + s];
            acc[i][0] = fmaf(p, y.x, acc[i][0]);
            acc[i][1] = fmaf(p, y.y, acc[i][1]);
            acc[i][2] = fmaf(p, y.z, acc[i][2]);
            acc[i][3] = fmaf(p, y.w, acc[i][3]);
        }
    }
    float4 bb = *reinterpret_cast<const float4*>(&b1[o0]);
    float* out = g_G1 + (size_t)b * 4096;
    float sums[4], ssqs[4];
    #pragma unroll
    for (int i = 0; i < 4; i++) {
        float v0 = acc[i][0] + bb.x, v1 = acc[i][1] + bb.y;
        float v2 = acc[i][2] + bb.z, v3 = acc[i][3] + bb.w;
        *reinterpret_cast<float4*>(&out[(d0 + i) * 64 + o0]) = make_float4(v0, v1, v2, v3);
        sums[i] = (v0 + v1) + (v2 + v3);
        ssqs[i] = fmaf(v0, v0, fmaf(v1, v1, fmaf(v2, v2, v3 * v3)));
    }
    #pragma unroll
    for (int off = 8; off >= 1; off >>= 1) {
        #pragma unroll
        for (int i = 0; i < 4; i++) {
            sums[i] += __shfl_xor_sync(0xffffffffu, sums[i], off);
            ssqs[i] += __shfl_xor_sync(0xffffffffu, ssqs[i], off);
        }
    }
    if ((t & 15) == 0) {
        #pragma unroll
        for (int i = 0; i < 4; i++) {
            atomicAdd(&g_sum1[d0 + i], sums[i]);
            atomicAdd(&g_ssq1[d0 + i], ssqs[i]);
        }
    }
}

// ---------------- K3: Z2[b] = relu(bn1(G1[b])) @ W2^T  (bn coeffs computed inline) ---
__global__ void k_gemm2(const float* __restrict__ W2, const float* __restrict__ g1,
                        const float* __restrict__ be1) {
    __shared__ float a1s[64], c1s[64];
    __shared__ __align__(16) float G1s[4096];
    __shared__ __align__(16) float W2t[64 * 36];   // W2t[o][j], j padded to 36
    int b = blockIdx.x, t = threadIdx.x;
    if (t < 64) {
        const float invn = 1.0f / (float)(B_ * C1);
        float m = g_sum1[t] * invn;
        float v = g_ssq1[t] * invn - m * m;
        float aa = g1[t] * rsqrtf(v + 1e-5f);
        a1s[t] = aa;
        c1s[t] = be1[t] - m * aa;
    }
    __syncthreads();
    const float* src = g_G1 + (size_t)b * 4096;
    for (int i = t; i < 4096; i += 256) {
        int d = i >> 6;
        G1s[i] = fmaxf(fmaf(src[i], a1s[d], c1s[d]), 0.f);
    }
    for (int i = t; i < 2048; i += 256) {
        int j = i >> 6, o = i & 63;
        W2t[o * 36 + j] = W2[i];
    }
    __syncthreads();
    int d0 = (t >> 3) * 2, j0 = (t & 7) * 4;
    float acc[2][4] = {};
    #pragma unroll 4
    for (int o = 0; o < 64; o++) {
        float4 w = *reinterpret_cast<const float4*>(&W2t[o * 36 + j0]);
        float gA = G1s[d0 * 64 + o];
        float gB = G1s[d0 * 64 + 64 + o];
        acc[0][0] = fmaf(gA, w.x, acc[0][0]); acc[0][1] = fmaf(gA, w.y, acc[0][1]);
        acc[0][2] = fmaf(gA, w.z, acc[0][2]); acc[0][3] = fmaf(gA, w.w, acc[0][3]);
        acc[1][0] = fmaf(gB, w.x, acc[1][0]); acc[1][1] = fmaf(gB, w.y, acc[1][1]);
        acc[1][2] = fmaf(gB, w.z, acc[1][2]); acc[1][3] = fmaf(gB, w.w, acc[1][3]);
    }
    float* out = g_Z2 + (size_t)b * 2048;
    *reinterpret_cast<float4*>(&out[d0 * 32 + j0]) =
        make_float4(acc[0][0], acc[0][1], acc[0][2], acc[0][3]);
    *reinterpret_cast<float4*>(&out[(d0 + 1) * 32 + j0]) =
        make_float4(acc[1][0], acc[1][1], acc[1][2], acc[1][3]);
}

// ---------------- K4: G2[b] = P @ Z2[b] + b2, with BN2 stats epilogue ----------------
__global__ void k_pgemm2(const float* __restrict__ b2) {
    __shared__ __align__(16) float Ps[4096];
    __shared__ __align__(16) float Zs[2048];
    int b = blockIdx.x, t = threadIdx.x;
    const float* src = g_Z2 + (size_t)b * 2048;
    for (int i = t; i < 4096; i += 256) Ps[i] = g_P[i];
    for (int i = t; i < 2048; i += 256) Zs[i] = src[i];
    __syncthreads();
    int d0 = (t >> 4) * 4, j0 = (t & 15) * 2;
    float acc[4][2] = {};
    #pragma unroll 4
    for (int s = 0; s < 64; s++) {
        float2 z = *reinterpret_cast<const float2*>(&Zs[s * 32 + j0]);
        #pragma unroll
        for (int i = 0; i < 4; i++) {
            float p = Ps[(d0 + i) * 64 + s];
            acc[i][0] = fmaf(p, z.x, acc[i][0]);
            acc[i][1] = fmaf(p, z.y, acc[i][1]);
        }
    }
    float2 bb = *reinterpret_cast<const float2*>(&b2[j0]);
    float* out = g_G2 + (size_t)b * 2048;
    float sums[4], ssqs[4];
    #pragma unroll
    for (int i = 0; i < 4; i++) {
        float v0 = acc[i][0] + bb.x, v1 = acc[i][1] + bb.y;
        *reinterpret_cast<float2*>(&out[(d0 + i) * 32 + j0]) = make_float2(v0, v1);
        sums[i] = v0 + v1;
        ssqs[i] = fmaf(v0, v0, v1 * v1);
    }
    #pragma unroll
    for (int off = 8; off >= 1; off >>= 1) {
        #pragma unroll
        for (int i = 0; i < 4; i++) {
            sums[i] += __shfl_xor_sync(0xffffffffu, sums[i], off);
            ssqs[i] += __shfl_xor_sync(0xffffffffu, ssqs[i], off);
        }
    }
    if ((t & 15) == 0) {
        #pragma unroll
        for (int i = 0; i < 4; i++) {
            atomicAdd(&g_sum2[d0 + i], sums[i]);
            atomicAdd(&g_ssq2[d0 + i], ssqs[i]);
        }
    }
}

// ---------------- K5: bn2 (inline coeffs) + relu + max-pool over nodes ----------------
__global__ void k_pool(const float* __restrict__ g2, const float* __restrict__ be2) {
    __shared__ float a2s[64], c2s[64];
    int t = threadIdx.x;
    if (t < 64) {
        const float invn = 1.0f / (float)(B_ * C2);
        float m = g_sum2[t] * invn;
        float v = g_ssq2[t] * invn - m * m;
        float aa = g2[t] * rsqrtf(v + 1e-5f);
        a2s[t] = aa;
        c2s[t] = be2[t] - m * aa;
    }
    __syncthreads();
    int bl = t >> 5, j = t & 31;
    int b = blockIdx.x * 8 + bl;
    const float* src = g_G2 + (size_t)b * 2048 + j;
    float m = 0.f;   // relu outputs are >= 0
    #pragma unroll 8
    for (int d = 0; d < 64; d++) {
        float v = fmaxf(fmaf(src[d * 32], a2s[d], c2s[d]), 0.f);
        m = fmaxf(m, v);
    }
    g_pool[b * 32 + j] = m;
}

// ---------------- MLP1 (scalar, 128x64 tile, 8x4/thread): H1 = relu(xf@Wl1^T+bl1) ----
__global__ __launch_bounds__(256)
void k_mlp1(const float* __restrict__ A, const float* __restrict__ Bw,
            const float* __restrict__ bias) {
    __shared__ __align__(16) float As[16 * 132];   // As[k][m], m=128 padded to 132
    __shared__ __align__(16) float Bs[16 * 68];    // Bs[k][n], n=64 padded to 68
    int t = threadIdx.x;
    int m0 = blockIdx.x * 128, n0 = blockIdx.y * 64;
    int tm = (t >> 4) * 8, tn = (t & 15) * 4;
    float acc[8][4] = {};
    for (int k0 = 0; k0 < DFP; k0 += 16) {
        #pragma unroll
        for (int rep = 0; rep < 8; rep++) {
            int i = t + rep * 256;          // 0..2047
            int r = i >> 4, kk = i & 15;
            As[kk * 132 + r] = A[(size_t)(m0 + r) * DFP + k0 + kk];
        }
        #pragma unroll
        for (int rep = 0; rep < 4; rep++) {
            int i = t + rep * 256;          // 0..1023
            int r = i >> 4, kk = i & 15;
            float bv = (n0 + r < H1D) ? Bw[(size_t)(n0 + r) * DFP + k0 + kk] : 0.f;
            Bs[kk * 68 + r] = bv;
        }
        __syncthreads();
        #pragma unroll
        for (int kk = 0; kk < 16; kk++) {
            float4 a0 = *reinterpret_cast<const float4*>(&As[kk * 132 + tm]);
            float4 a1 = *reinterpret_cast<const float4*>(&As[kk * 132 + tm + 4]);
            float4 b  = *reinterpret_cast<const float4*>(&Bs[kk * 68 + tn]);
            acc[0][0] = fmaf(a0.x, b.x, acc[0][0]); acc[0][1] = fmaf(a0.x, b.y, acc[0][1]);
            acc[0][2] = fmaf(a0.x, b.z, acc[0][2]); acc[0][3] = fmaf(a0.x, b.w, acc[0][3]);
            acc[1][0] = fmaf(a0.y, b.x, acc[1][0]); acc[1][1] = fmaf(a0.y, b.y, acc[1][1]);
            acc[1][2] = fmaf(a0.y, b.z, acc[1][2]); acc[1][3] = fmaf(a0.y, b.w, acc[1][3]);
            acc[2][0] = fmaf(a0.z, b.x, acc[2][0]); acc[2][1] = fmaf(a0.z, b.y, acc[2][1]);
            acc[2][2] = fmaf(a0.z, b.z, acc[2][2]); acc[2][3] = fmaf(a0.z, b.w, acc[2][3]);
            acc[3][0] = fmaf(a0.w, b.x, acc[3][0]); acc[3][1] = fmaf(a0.w, b.y, acc[3][1]);
            acc[3][2] = fmaf(a0.w, b.z, acc[3][2]); acc[3][3] = fmaf(a0.w, b.w, acc[3][3]);
            acc[4][0] = fmaf(a1.x, b.x, acc[4][0]); acc[4][1] = fmaf(a1.x, b.y, acc[4][1]);
            acc[4][2] = fmaf(a1.x, b.z, acc[4][2]); acc[4][3] = fmaf(a1.x, b.w, acc[4][3]);
            acc[5][0] = fmaf(a1.y, b.x, acc[5][0]); acc[5][1] = fmaf(a1.y, b.y, acc[5][1]);
            acc[5][2] = fmaf(a1.y, b.z, acc[5][2]); acc[5][3] = fmaf(a1.y, b.w, acc[5][3]);
            acc[6][0] = fmaf(a1.z, b.x, acc[6][0]); acc[6][1] = fmaf(a1.z, b.y, acc[6][1]);
            acc[6][2] = fmaf(a1.z, b.z, acc[6][2]); acc[6][3] = fmaf(a1.z, b.w, acc[6][3]);
            acc[7][0] = fmaf(a1.w, b.x, acc[7][0]); acc[7][1] = fmaf(a1.w, b.y, acc[7][1]);
            acc[7][2] = fmaf(a1.w, b.z, acc[7][2]); acc[7][3] = fmaf(a1.w, b.w, acc[7][3]);
        }
        __syncthreads();
    }
    #pragma unroll
    for (int i = 0; i < 8; i++) {
        int row = m0 + tm + i;
        float* c = g_H1 + (size_t)row * H1D;
        #pragma unroll
        for (int j = 0; j < 4; j++) {
            int col = n0 + tn + j;
            if (col < H1D) c[col] = fmaxf(acc[i][j] + __ldg(&bias[col]), 0.f);
        }
    }
}

// ---------------- MLP2 (scalar 64x64): H2 = relu(H1 @ Wl2^T + bl2) ----------------
__global__ void k_mlp2(const float* __restrict__ Bw, const float* __restrict__ bias) {
    __shared__ __align__(16) float As[16 * 68];
    __shared__ __align__(16) float Bs[16 * 68];
    const float* A = g_H1;
    float* C = g_H2;
    int m0 = blockIdx.x * 64;
    int t = threadIdx.x;
    int tm = (t >> 4) * 4, tn = (t & 15) * 4;
    float acc[4][4] = {};
    for (int k0 = 0; k0 < H1D; k0 += 16) {
        for (int i = t; i < 1024; i += 256) {
            int r = i >> 4, kk = i & 15;
            As[kk * 68 + r] = A[(size_t)(m0 + r) * H1D + k0 + kk];
            Bs[kk * 68 + r] = Bw[(size_t)r * H1D + k0 + kk];
        }
        __syncthreads();
        #pragma unroll
        for (int kk = 0; kk < 16; kk++) {
            float4 a = *reinterpret_cast<const float4*>(&As[kk * 68 + tm]);
            float4 b = *reinterpret_cast<const float4*>(&Bs[kk * 68 + tn]);
            acc[0][0] = fmaf(a.x, b.x, acc[0][0]); acc[0][1] = fmaf(a.x, b.y, acc[0][1]);
            acc[0][2] = fmaf(a.x, b.z, acc[0][2]); acc[0][3] = fmaf(a.x, b.w, acc[0][3]);
            acc[1][0] = fmaf(a.y, b.x, acc[1][0]); acc[1][1] = fmaf(a.y, b.y, acc[1][1]);
            acc[1][2] = fmaf(a.y, b.z, acc[1][2]); acc[1][3] = fmaf(a.y, b.w, acc[1][3]);
            acc[2][0] = fmaf(a.z, b.x, acc[2][0]); acc[2][1] = fmaf(a.z, b.y, acc[2][1]);
            acc[2][2] = fmaf(a.z, b.z, acc[2][2]); acc[2][3] = fmaf(a.z, b.w, acc[2][3]);
            acc[3][0] = fmaf(a.w, b.x, acc[3][0]); acc[3][1] = fmaf(a.w, b.y, acc[3][1]);
            acc[3][2] = fmaf(a.w, b.z, acc[3][2]); acc[3][3] = fmaf(a.w, b.w, acc[3][3]);
        }
        __syncthreads();
    }
    #pragma unroll
    for (int i = 0; i < 4; i++) {
        int row = m0 + tm + i;
        #pragma unroll
        for (int j = 0; j < 4; j++) {
            int col = tn + j;
            C[(size_t)row * H2D + col] = fmaxf(acc[i][j] + __ldg(&bias[col]), 0.f);
        }
    }
}

// ---------------- final: out = [pool, H2] @ Wfc^T + bfc ----------------
__global__ void k_final(const float* __restrict__ Wfc, const float* __restrict__ bfc,
                        float* __restrict__ out) {
    __shared__ float Ws[192];
    int t = threadIdx.x;
    if (t < 192) Ws[t] = Wfc[t];
    __syncthreads();
    int b = blockIdx.x * 256 + t;
    float a0 = __ldg(&bfc[0]), a1 = __ldg(&bfc[1]);
    const float* pp = g_pool + b * 32;
    const float* hh = g_H2 + b * 64;
    #pragma unroll
    for (int j = 0; j < 32; j++) {
        float v = pp[j];
        a0 = fmaf(v, Ws[j], a0);
        a1 = fmaf(v, Ws[96 + j], a1);
    }
    #pragma unroll
    for (int j = 0; j < 64; j++) {
        float v = hh[j];
        a0 = fmaf(v, Ws[32 + j], a0);
        a1 = fmaf(v, Ws[128 + j], a1);
    }
    out[b * 2]     = a0;
    out[b * 2 + 1] = a1;
}

// ---------------- launch ----------------
extern "C" void kernel_launch(void* const* d_in, const int* in_sizes, int n_in,
                              void* d_out, int out_size) {
    const float* xf  = (const float*)d_in[0];
    const float* xn  = (const float*)d_in[1];
    const int*   el  = (const int*)  d_in[2];
    const float* W1  = (const float*)d_in[3];
    const float* b1  = (const float*)d_in[4];
    const float* g1  = (const float*)d_in[5];
    const float* be1 = (const float*)d_in[6];
    const float* W2  = (const float*)d_in[7];
    const float* b2  = (const float*)d_in[8];
    const float* g2  = (const float*)d_in[9];
    const float* be2 = (const float*)d_in[10];
    const float* Wl1 = (const float*)d_in[11];
    const float* bl1 = (const float*)d_in[12];
    const float* Wl2 = (const float*)d_in[13];
    const float* bl2 = (const float*)d_in[14];
    const float* Wfc = (const float*)d_in[15];
    const float* bfc = (const float*)d_in[16];
    float* out = (float*)d_out;

    k_prep<<<1, 256>>>(el);

    // graph path (BN stats fused into pgemm epilogues; coeffs computed inline)
    k_gemm1<<<(B_ * NNODE) / 64, 256>>>(xn, W1);
    k_pgemm1<<<B_, 256>>>(b1);
    k_gemm2<<<B_, 256>>>(W2, g1, be1);
    k_pgemm2<<<B_, 256>>>(b2);
    k_pool<<<B_ / 8, 256>>>(g2, be2);

    // fingerprint MLP path
    k_mlp1<<<dim3(B_ / 128, (H1D + 63) / 64), 256>>>(xf, Wl1, bl1);
    k_mlp2<<<B_ / 64, 256>>>(Wl2, bl2);

    k_final<<<B_ / 256, 256>>>(Wfc, bfc, out);
}

// round 13
// speedup vs baseline: 1.1556x; 1.1556x over previous
#include <cuda_runtime.h>
#include <cuda_bf16.h>

#define B_    4096
#define NNODE 64
#define FIN   67
#define C1    64
#define C2    32
#define DFP   2048
#define H1D   400
#define H1PAD 448
#define H2D   64
#define NEDGE 512

// ---------------- scratch (device globals; no allocations allowed) ----------------
__device__ float g_P [NNODE * NNODE];
__device__ float g_Y1[B_ * NNODE * C1];
__device__ float g_G1[B_ * NNODE * C1];
__device__ float g_Z2[B_ * NNODE * C2];
__device__ float g_G2[B_ * NNODE * C2];
__device__ float g_pool[B_ * C2];
__device__ float g_H1[B_ * H1D];
__device__ float g_H2[B_ * H2D];
__device__ float g_sum1[NNODE], g_ssq1[NNODE], g_sum2[NNODE], g_ssq2[NNODE];
// bf16-split packed operands for mlp1 (u32 = 2 bf16 along k)
__device__ unsigned g_Ah[B_ * (DFP / 2)];
__device__ unsigned g_Al[B_ * (DFP / 2)];
__device__ unsigned g_Bh[H1PAD * (DFP / 2)];
__device__ unsigned g_Bl[H1PAD * (DFP / 2)];

// ---------------- K0: build P from edge list, zero stats ----------------
__global__ void k_prep(const int* __restrict__ el) {
    __shared__ float deg[NNODE];
    __shared__ float dinv[NNODE];
    __shared__ float Ps[NNODE * NNODE];
    int t = threadIdx.x;
    if (t < NNODE) deg[t] = 0.f;
    for (int i = t; i < NNODE * NNODE; i += 256) Ps[i] = 0.f;
    __syncthreads();
    for (int i = t; i < NEDGE + NNODE; i += 256) {
        int d = (i < NEDGE) ? el[NEDGE + i] : (i - NEDGE);
        atomicAdd(&deg[d], 1.f);
    }
    __syncthreads();
    if (t < NNODE) dinv[t] = (deg[t] > 0.f) ? rsqrtf(deg[t]) : 0.f;
    __syncthreads();
    for (int i = t; i < NEDGE + NNODE; i += 256) {
        int s = (i < NEDGE) ? el[i] : (i - NEDGE);
        int d = (i < NEDGE) ? el[NEDGE + i] : (i - NEDGE);
        atomicAdd(&Ps[d * NNODE + s], dinv[s] * dinv[d]);
    }
    __syncthreads();
    for (int i = t; i < NNODE * NNODE; i += 256) g_P[i] = Ps[i];
    if (t < NNODE) { g_sum1[t] = 0.f; g_ssq1[t] = 0.f; g_sum2[t] = 0.f; g_ssq2[t] = 0.f; }
}

// ---------------- bf16 split helper: x -> (hi, lo) packed pairs ----------------
__device__ __forceinline__ uint2 split2(float x, float y) {
    __nv_bfloat16 hx = __float2bfloat16_rn(x), hy = __float2bfloat16_rn(y);
    float rx = x - __bfloat162float(hx), ry = y - __bfloat162float(hy);
    __nv_bfloat16 lx = __float2bfloat16_rn(rx), ly = __float2bfloat16_rn(ry);
    unsigned hi = ((unsigned)__bfloat16_as_ushort(hy) << 16) | __bfloat16_as_ushort(hx);
    unsigned lo = ((unsigned)__bfloat16_as_ushort(ly) << 16) | __bfloat16_as_ushort(lx);
    return make_uint2(hi, lo);
}

// ---------------- pack xf into hi/lo bf16 pairs ----------------
__global__ void k_pack_a(const float* __restrict__ xf) {
    int idx = blockIdx.x * 256 + threadIdx.x;       // 0 .. B_*1024-1
    int row = idx >> 10, kc = idx & 1023;
    float2 v = *reinterpret_cast<const float2*>(&xf[(size_t)row * DFP + kc * 2]);
    uint2 s = split2(v.x, v.y);
    g_Ah[idx] = s.x; g_Al[idx] = s.y;
}

// ---------------- pack Wl1 (padded to 448 rows with zeros) ----------------
__global__ void k_pack_b(const float* __restrict__ Wl1) {
    int idx = blockIdx.x * 256 + threadIdx.x;       // 0 .. 448*1024-1
    int n = idx >> 10, kc = idx & 1023;
    float2 v = make_float2(0.f, 0.f);
    if (n < H1D) v = *reinterpret_cast<const float2*>(&Wl1[(size_t)n * DFP + kc * 2]);
    uint2 s = split2(v.x, v.y);
    g_Bh[idx] = s.x; g_Bl[idx] = s.y;
}

// ---------------- K1: Y1 = X @ W1^T  (M=262144, K=67, N=64) ----------------
__global__ void k_gemm1(const float* __restrict__ X, const float* __restrict__ W1) {
    __shared__ __align__(16) float As[FIN * 68];
    __shared__ __align__(16) float Ws[FIN * 68];
    int t = threadIdx.x;
    int m0 = blockIdx.x * 64;
    const float* Xt = X + (size_t)m0 * FIN;
    for (int i = t; i < 64 * FIN; i += 256) {
        int r = i / FIN, k = i - r * FIN;
        As[k * 68 + r] = Xt[i];
    }
    for (int i = t; i < 64 * FIN; i += 256) {
        int n = i / FIN, k = i - n * FIN;
        Ws[k * 68 + n] = W1[i];
    }
    __syncthreads();
    int tm = (t >> 4) * 4, tn = (t & 15) * 4;
    float acc[4][4] = {};
    for (int k = 0; k < FIN; k++) {
        float4 a = *reinterpret_cast<const float4*>(&As[k * 68 + tm]);
        float4 b = *reinterpret_cast<const float4*>(&Ws[k * 68 + tn]);
        acc[0][0] = fmaf(a.x, b.x, acc[0][0]); acc[0][1] = fmaf(a.x, b.y, acc[0][1]);
        acc[0][2] = fmaf(a.x, b.z, acc[0][2]); acc[0][3] = fmaf(a.x, b.w, acc[0][3]);
        acc[1][0] = fmaf(a.y, b.x, acc[1][0]); acc[1][1] = fmaf(a.y, b.y, acc[1][1]);
        acc[1][2] = fmaf(a.y, b.z, acc[1][2]); acc[1][3] = fmaf(a.y, b.w, acc[1][3]);
        acc[2][0] = fmaf(a.z, b.x, acc[2][0]); acc[2][1] = fmaf(a.z, b.y, acc[2][1]);
        acc[2][2] = fmaf(a.z, b.z, acc[2][2]); acc[2][3] = fmaf(a.z, b.w, acc[2][3]);
        acc[3][0] = fmaf(a.w, b.x, acc[3][0]); acc[3][1] = fmaf(a.w, b.y, acc[3][1]);
        acc[3][2] = fmaf(a.w, b.z, acc[3][2]); acc[3][3] = fmaf(a.w, b.w, acc[3][3]);
    }
    #pragma unroll
    for (int i = 0; i < 4; i++) {
        float4 v = make_float4(acc[i][0], acc[i][1], acc[i][2], acc[i][3]);
        *reinterpret_cast<float4*>(&g_Y1[(size_t)(m0 + tm + i) * 64 + tn]) = v;
    }
}

// ---------------- K2: G1[b] = P @ Y1[b] + b1, with BN1 stats epilogue ----------------
__global__ void k_pgemm1(const float* __restrict__ b1) {
    __shared__ __align__(16) float Ps[4096];
    __shared__ __align__(16) float Ys[4096];
    int b = blockIdx.x, t = threadIdx.x;
    const float* src = g_Y1 + (size_t)b * 4096;
    for (int i = t; i < 4096; i += 256) { Ps[i] = g_P[i]; Ys[i] = src[i]; }
    __syncthreads();
    int d0 = (t >> 4) * 4, o0 = (t & 15) * 4;
    float acc[4][4] = {};
    #pragma unroll 4
    for (int s = 0; s < 64; s++) {
        float4 y = *reinterpret_cast<const float4*>(&Ys[s * 64 + o0]);
        #pragma unroll
        for (int i = 0; i < 4; i++) {
            float p = Ps[(d0 + i) * 64 + s];
            acc[i][0] = fmaf(p, y.x, acc[i][0]);
            acc[i][1] = fmaf(p, y.y, acc[i][1]);
            acc[i][2] = fmaf(p, y.z, acc[i][2]);
            acc[i][3] = fmaf(p, y.w, acc[i][3]);
        }
    }
    float4 bb = *reinterpret_cast<const float4*>(&b1[o0]);
    float* out = g_G1 + (size_t)b * 4096;
    float sums[4], ssqs[4];
    #pragma unroll
    for (int i = 0; i < 4; i++) {
        float v0 = acc[i][0] + bb.x, v1 = acc[i][1] + bb.y;
        float v2 = acc[i][2] + bb.z, v3 = acc[i][3] + bb.w;
        *reinterpret_cast<float4*>(&out[(d0 + i) * 64 + o0]) = make_float4(v0, v1, v2, v3);
        sums[i] = (v0 + v1) + (v2 + v3);
        ssqs[i] = fmaf(v0, v0, fmaf(v1, v1, fmaf(v2, v2, v3 * v3)));
    }
    #pragma unroll
    for (int off = 8; off >= 1; off >>= 1) {
        #pragma unroll
        for (int i = 0; i < 4; i++) {
            sums[i] += __shfl_xor_sync(0xffffffffu, sums[i], off);
            ssqs[i] += __shfl_xor_sync(0xffffffffu, ssqs[i], off);
        }
    }
    if ((t & 15) == 0) {
        #pragma unroll
        for (int i = 0; i < 4; i++) {
            atomicAdd(&g_sum1[d0 + i], sums[i]);
            atomicAdd(&g_ssq1[d0 + i], ssqs[i]);
        }
    }
}

// ---------------- K3: Z2[b] = relu(bn1(G1[b])) @ W2^T  (bn coeffs inline) ----------
__global__ void k_gemm2(const float* __restrict__ W2, const float* __restrict__ g1,
                        const float* __restrict__ be1) {
    __shared__ float a1s[64], c1s[64];
    __shared__ __align__(16) float G1s[4096];
    __shared__ __align__(16) float W2t[64 * 36];
    int b = blockIdx.x, t = threadIdx.x;
    if (t < 64) {
        const float invn = 1.0f / (float)(B_ * C1);
        float m = g_sum1[t] * invn;
        float v = g_ssq1[t] * invn - m * m;
        float aa = g1[t] * rsqrtf(v + 1e-5f);
        a1s[t] = aa;
        c1s[t] = be1[t] - m * aa;
    }
    __syncthreads();
    const float* src = g_G1 + (size_t)b * 4096;
    for (int i = t; i < 4096; i += 256) {
        int d = i >> 6;
        G1s[i] = fmaxf(fmaf(src[i], a1s[d], c1s[d]), 0.f);
    }
    for (int i = t; i < 2048; i += 256) {
        int j = i >> 6, o = i & 63;
        W2t[o * 36 + j] = W2[i];
    }
    __syncthreads();
    int d0 = (t >> 3) * 2, j0 = (t & 7) * 4;
    float acc[2][4] = {};
    #pragma unroll 4
    for (int o = 0; o < 64; o++) {
        float4 w = *reinterpret_cast<const float4*>(&W2t[o * 36 + j0]);
        float gA = G1s[d0 * 64 + o];
        float gB = G1s[d0 * 64 + 64 + o];
        acc[0][0] = fmaf(gA, w.x, acc[0][0]); acc[0][1] = fmaf(gA, w.y, acc[0][1]);
        acc[0][2] = fmaf(gA, w.z, acc[0][2]); acc[0][3] = fmaf(gA, w.w, acc[0][3]);
        acc[1][0] = fmaf(gB, w.x, acc[1][0]); acc[1][1] = fmaf(gB, w.y, acc[1][1]);
        acc[1][2] = fmaf(gB, w.z, acc[1][2]); acc[1][3] = fmaf(gB, w.w, acc[1][3]);
    }
    float* out = g_Z2 + (size_t)b * 2048;
    *reinterpret_cast<float4*>(&out[d0 * 32 + j0]) =
        make_float4(acc[0][0], acc[0][1], acc[0][2], acc[0][3]);
    *reinterpret_cast<float4*>(&out[(d0 + 1) * 32 + j0]) =
        make_float4(acc[1][0], acc[1][1], acc[1][2], acc[1][3]);
}

// ---------------- K4: G2[b] = P @ Z2[b] + b2, with BN2 stats epilogue ----------------
__global__ void k_pgemm2(const float* __restrict__ b2) {
    __shared__ __align__(16) float Ps[4096];
    __shared__ __align__(16) float Zs[2048];
    int b = blockIdx.x, t = threadIdx.x;
    const float* src = g_Z2 + (size_t)b * 2048;
    for (int i = t; i < 4096; i += 256) Ps[i] = g_P[i];
    for (int i = t; i < 2048; i += 256) Zs[i] = src[i];
    __syncthreads();
    int d0 = (t >> 4) * 4, j0 = (t & 15) * 2;
    float acc[4][2] = {};
    #pragma unroll 4
    for (int s = 0; s < 64; s++) {
        float2 z = *reinterpret_cast<const float2*>(&Zs[s * 32 + j0]);
        #pragma unroll
        for (int i = 0; i < 4; i++) {
            float p = Ps[(d0 + i) * 64 + s];
            acc[i][0] = fmaf(p, z.x, acc[i][0]);
            acc[i][1] = fmaf(p, z.y, acc[i][1]);
        }
    }
    float2 bb = *reinterpret_cast<const float2*>(&b2[j0]);
    float* out = g_G2 + (size_t)b * 2048;
    float sums[4], ssqs[4];
    #pragma unroll
    for (int i = 0; i < 4; i++) {
        float v0 = acc[i][0] + bb.x, v1 = acc[i][1] + bb.y;
        *reinterpret_cast<float2*>(&out[(d0 + i) * 32 + j0]) = make_float2(v0, v1);
        sums[i] = v0 + v1;
        ssqs[i] = fmaf(v0, v0, v1 * v1);
    }
    #pragma unroll
    for (int off = 8; off >= 1; off >>= 1) {
        #pragma unroll
        for (int i = 0; i < 4; i++) {
            sums[i] += __shfl_xor_sync(0xffffffffu, sums[i], off);
            ssqs[i] += __shfl_xor_sync(0xffffffffu, ssqs[i], off);
        }
    }
    if ((t & 15) == 0) {
        #pragma unroll
        for (int i = 0; i < 4; i++) {
            atomicAdd(&g_sum2[d0 + i], sums[i]);
            atomicAdd(&g_ssq2[d0 + i], ssqs[i]);
        }
    }
}

// ---------------- K5: bn2 (inline coeffs) + relu + max-pool over nodes ---------------
__global__ void k_pool(const float* __restrict__ g2, const float* __restrict__ be2) {
    __shared__ float a2s[64], c2s[64];
    int t = threadIdx.x;
    if (t < 64) {
        const float invn = 1.0f / (float)(B_ * C2);
        float m = g_sum2[t] * invn;
        float v = g_ssq2[t] * invn - m * m;
        float aa = g2[t] * rsqrtf(v + 1e-5f);
        a2s[t] = aa;
        c2s[t] = be2[t] - m * aa;
    }
    __syncthreads();
    int bl = t >> 5, j = t & 31;
    int b = blockIdx.x * 8 + bl;
    const float* src = g_G2 + (size_t)b * 2048 + j;
    float m = 0.f;
    #pragma unroll 8
    for (int d = 0; d < 64; d++) {
        float v = fmaxf(fmaf(src[d * 32], a2s[d], c2s[d]), 0.f);
        m = fmaxf(m, v);
    }
    g_pool[b * 32 + j] = m;
}

// ---------------- MLP1 tensor-core: H1 = relu(xf @ Wl1^T + bl1), bf16 split ----------
#define MMA_BF16(d, a, b) \
    asm volatile("mma.sync.aligned.m16n8k16.row.col.f32.bf16.bf16.f32 " \
        "{%0,%1,%2,%3},{%4,%5,%6,%7},{%8,%9},{%0,%1,%2,%3};\n" \
        : "+f"(d[0]), "+f"(d[1]), "+f"(d[2]), "+f"(d[3]) \
        : "r"(a[0]), "r"(a[1]), "r"(a[2]), "r"(a[3]), "r"(b[0]), "r"(b[1]))

__global__ __launch_bounds__(256, 2)
void k_mlp1_tc(const float* __restrict__ bias) {
    __shared__ unsigned Ah[128 * 20], Al[128 * 20];   // [row][u32 k-col], stride 20
    __shared__ unsigned Bh[64 * 20],  Bl[64 * 20];
    int t = threadIdx.x;
    int m0 = blockIdx.x * 128, n0 = blockIdx.y * 64;
    int wid = t >> 5, lane = t & 31;
    int wm = (wid & 3) * 32, wn = (wid >> 2) * 32;
    int g = lane >> 2, c = lane & 3;
    int arow = t >> 2, ac4 = (t & 3) * 4;

    float acc[2][4][4] = {};

    for (int ch = 0; ch < 64; ch++) {
        __syncthreads();
        int kbase = ch * 16;
        #pragma unroll
        for (int rep = 0; rep < 2; rep++) {
            int row = arow + rep * 64;
            size_t gi = (size_t)(m0 + row) * 1024 + kbase + ac4;
            *reinterpret_cast<uint4*>(&Ah[row * 20 + ac4]) =
                *reinterpret_cast<const uint4*>(&g_Ah[gi]);
            *reinterpret_cast<uint4*>(&Al[row * 20 + ac4]) =
                *reinterpret_cast<const uint4*>(&g_Al[gi]);
        }
        {
            size_t gi = (size_t)(n0 + arow) * 1024 + kbase + ac4;   // arow < 64 here? no:
            // arow spans 0..63 only for t<256/4... arow = t>>2 in 0..63 for t<256. OK.
            *reinterpret_cast<uint4*>(&Bh[arow * 20 + ac4]) =
                *reinterpret_cast<const uint4*>(&g_Bh[gi]);
            *reinterpret_cast<uint4*>(&Bl[arow * 20 + ac4]) =
                *reinterpret_cast<const uint4*>(&g_Bl[gi]);
        }
        __syncthreads();
        #pragma unroll
        for (int kk = 0; kk < 2; kk++) {
            int ko = kk * 8;
            unsigned ah[2][4], al[2][4], bh[4][2], bl[4][2];
            #pragma unroll
            for (int mi = 0; mi < 2; mi++) {
                int r = wm + mi * 16 + g;
                ah[mi][0] = Ah[r * 20 + c + ko];
                ah[mi][1] = Ah[(r + 8) * 20 + c + ko];
                ah[mi][2] = Ah[r * 20 + c + 4 + ko];
                ah[mi][3] = Ah[(r + 8) * 20 + c + 4 + ko];
                al[mi][0] = Al[r * 20 + c + ko];
                al[mi][1] = Al[(r + 8) * 20 + c + ko];
                al[mi][2] = Al[r * 20 + c + 4 + ko];
                al[mi][3] = Al[(r + 8) * 20 + c + 4 + ko];
            }
            #pragma unroll
            for (int ni = 0; ni < 4; ni++) {
                int n = wn + ni * 8 + g;
                bh[ni][0] = Bh[n * 20 + c + ko];
                bh[ni][1] = Bh[n * 20 + c + 4 + ko];
                bl[ni][0] = Bl[n * 20 + c + ko];
                bl[ni][1] = Bl[n * 20 + c + 4 + ko];
            }
            #pragma unroll
            for (int mi = 0; mi < 2; mi++) {
                #pragma unroll
                for (int ni = 0; ni < 4; ni++) {
                    MMA_BF16(acc[mi][ni], ah[mi], bh[ni]);
                    MMA_BF16(acc[mi][ni], ah[mi], bl[ni]);
                    MMA_BF16(acc[mi][ni], al[mi], bh[ni]);
                }
            }
        }
    }

    #pragma unroll
    for (int mi = 0; mi < 2; mi++) {
        #pragma unroll
        for (int ni = 0; ni < 4; ni++) {
            int col = n0 + wn + ni * 8 + 2 * c;
            if (col < H1D) {
                float bv0 = __ldg(&bias[col]), bv1 = __ldg(&bias[col + 1]);
                int r0 = m0 + wm + mi * 16 + g;
                float* p0 = g_H1 + (size_t)r0 * H1D + col;
                float* p1 = g_H1 + (size_t)(r0 + 8) * H1D + col;
                p0[0] = fmaxf(acc[mi][ni][0] + bv0, 0.f);
                p0[1] = fmaxf(acc[mi][ni][1] + bv1, 0.f);
                p1[0] = fmaxf(acc[mi][ni][2] + bv0, 0.f);
                p1[1] = fmaxf(acc[mi][ni][3] + bv1, 0.f);
            }
        }
    }
}

// ---------------- MLP2 (scalar 64x64): H2 = relu(H1 @ Wl2^T + bl2) ----------------
__global__ void k_mlp2(const float* __restrict__ Bw, const float* __restrict__ bias) {
    __shared__ __align__(16) float As[16 * 68];
    __shared__ __align__(16) float Bs[16 * 68];
    const float* A = g_H1;
    float* C = g_H2;
    int m0 = blockIdx.x * 64;
    int t = threadIdx.x;
    int tm = (t >> 4) * 4, tn = (t & 15) * 4;
    float acc[4][4] = {};
    for (int k0 = 0; k0 < H1D; k0 += 16) {
        for (int i = t; i < 1024; i += 256) {
            int r = i >> 4, kk = i & 15;
            As[kk * 68 + r] = A[(size_t)(m0 + r) * H1D + k0 + kk];
            Bs[kk * 68 + r] = Bw[(size_t)r * H1D + k0 + kk];
        }
        __syncthreads();
        #pragma unroll
        for (int kk = 0; kk < 16; kk++) {
            float4 a = *reinterpret_cast<const float4*>(&As[kk * 68 + tm]);
            float4 b = *reinterpret_cast<const float4*>(&Bs[kk * 68 + tn]);
            acc[0][0] = fmaf(a.x, b.x, acc[0][0]); acc[0][1] = fmaf(a.x, b.y, acc[0][1]);
            acc[0][2] = fmaf(a.x, b.z, acc[0][2]); acc[0][3] = fmaf(a.x, b.w, acc[0][3]);
            acc[1][0] = fmaf(a.y, b.x, acc[1][0]); acc[1][1] = fmaf(a.y, b.y, acc[1][1]);
            acc[1][2] = fmaf(a.y, b.z, acc[1][2]); acc[1][3] = fmaf(a.y, b.w, acc[1][3]);
            acc[2][0] = fmaf(a.z, b.x, acc[2][0]); acc[2][1] = fmaf(a.z, b.y, acc[2][1]);
            acc[2][2] = fmaf(a.z, b.z, acc[2][2]); acc[2][3] = fmaf(a.z, b.w, acc[2][3]);
            acc[3][0] = fmaf(a.w, b.x, acc[3][0]); acc[3][1] = fmaf(a.w, b.y, acc[3][1]);
            acc[3][2] = fmaf(a.w, b.z, acc[3][2]); acc[3][3] = fmaf(a.w, b.w, acc[3][3]);
        }
        __syncthreads();
    }
    #pragma unroll
    for (int i = 0; i < 4; i++) {
        int row = m0 + tm + i;
        #pragma unroll
        for (int j = 0; j < 4; j++) {
            int col = tn + j;
            C[(size_t)row * H2D + col] = fmaxf(acc[i][j] + __ldg(&bias[col]), 0.f);
        }
    }
}

// ---------------- final: out = [pool, H2] @ Wfc^T + bfc ----------------
__global__ void k_final(const float* __restrict__ Wfc, const float* __restrict__ bfc,
                        float* __restrict__ out) {
    __shared__ float Ws[192];
    int t = threadIdx.x;
    if (t < 192) Ws[t] = Wfc[t];
    __syncthreads();
    int b = blockIdx.x * 256 + t;
    float a0 = __ldg(&bfc[0]), a1 = __ldg(&bfc[1]);
    const float* pp = g_pool + b * 32;
    const float* hh = g_H2 + b * 64;
    #pragma unroll
    for (int j = 0; j < 32; j++) {
        float v = pp[j];
        a0 = fmaf(v, Ws[j], a0);
        a1 = fmaf(v, Ws[96 + j], a1);
    }
    #pragma unroll
    for (int j = 0; j < 64; j++) {
        float v = hh[j];
        a0 = fmaf(v, Ws[32 + j], a0);
        a1 = fmaf(v, Ws[128 + j], a1);
    }
    out[b * 2]     = a0;
    out[b * 2 + 1] = a1;
}

// ---------------- launch ----------------
extern "C" void kernel_launch(void* const* d_in, const int* in_sizes, int n_in,
                              void* d_out, int out_size) {
    const float* xf  = (const float*)d_in[0];
    const float* xn  = (const float*)d_in[1];
    const int*   el  = (const int*)  d_in[2];
    const float* W1  = (const float*)d_in[3];
    const float* b1  = (const float*)d_in[4];
    const float* g1  = (const float*)d_in[5];
    const float* be1 = (const float*)d_in[6];
    const float* W2  = (const float*)d_in[7];
    const float* b2  = (const float*)d_in[8];
    const float* g2  = (const float*)d_in[9];
    const float* be2 = (const float*)d_in[10];
    const float* Wl1 = (const float*)d_in[11];
    const float* bl1 = (const float*)d_in[12];
    const float* Wl2 = (const float*)d_in[13];
    const float* bl2 = (const float*)d_in[14];
    const float* Wfc = (const float*)d_in[15];
    const float* bfc = (const float*)d_in[16];
    float* out = (float*)d_out;

    k_prep<<<1, 256>>>(el);
    // pre-split mlp1 operands into bf16 hi/lo
    k_pack_b<<<(H1PAD * (DFP / 2)) / 256, 256>>>(Wl1);
    k_pack_a<<<(B_ * (DFP / 2)) / 256, 256>>>(xf);

    // graph path (BN stats fused into pgemm epilogues; coeffs computed inline)
    k_gemm1<<<(B_ * NNODE) / 64, 256>>>(xn, W1);
    k_pgemm1<<<B_, 256>>>(b1);
    k_gemm2<<<B_, 256>>>(W2, g1, be1);
    k_pgemm2<<<B_, 256>>>(b2);
    k_pool<<<B_ / 8, 256>>>(g2, be2);

    // fingerprint MLP path (tensor-core mlp1)
    k_mlp1_tc<<<dim3(B_ / 128, H1PAD / 64), 256>>>(bl1);
    k_mlp2<<<B_ / 64, 256>>>(Wl2, bl2);

    k_final<<<B_ / 256, 256>>>(Wfc, bfc, out);
}

// round 14
// speedup vs baseline: 1.4237x; 1.2320x over previous
#include <cuda_runtime.h>
#include <cuda_bf16.h>

#define B_    4096
#define NNODE 64
#define FIN   67
#define C1    64
#define C2    32
#define DFP   2048
#define H1D   400
#define H1PAD 448
#define H2D   64
#define NEDGE 512

// ---------------- scratch (device globals; no allocations allowed) ----------------
__device__ float g_P [NNODE * NNODE];
__device__ float g_G1[B_ * NNODE * C1];
__device__ float g_G2[B_ * NNODE * C2];
__device__ float g_pool[B_ * C2];
__device__ float g_H1[B_ * H1D];
__device__ float g_H2[B_ * H2D];
__device__ float g_sum1[NNODE], g_ssq1[NNODE], g_sum2[NNODE], g_ssq2[NNODE];
// bf16-split packed operands (u32 = 2 bf16 along k)
__device__ unsigned g_Ah[B_ * (DFP / 2)];
__device__ unsigned g_Al[B_ * (DFP / 2)];
__device__ unsigned g_Bh[H1PAD * (DFP / 2)];
__device__ unsigned g_Bl[H1PAD * (DFP / 2)];
__device__ unsigned g_W1h[64 * 40], g_W1l[64 * 40];   // W1 [64][K80 pad] packed
__device__ unsigned g_Ph [64 * 32], g_Pl [64 * 32];   // P  [64][K64]     packed
__device__ unsigned g_W2h[32 * 32], g_W2l[32 * 32];   // W2 [32][K64]     packed

// ---------------- helpers ----------------
__device__ __forceinline__ uint2 split2(float x, float y) {
    __nv_bfloat16 hx = __float2bfloat16_rn(x), hy = __float2bfloat16_rn(y);
    float rx = x - __bfloat162float(hx), ry = y - __bfloat162float(hy);
    __nv_bfloat16 lx = __float2bfloat16_rn(rx), ly = __float2bfloat16_rn(ry);
    unsigned hi = ((unsigned)__bfloat16_as_ushort(hy) << 16) | __bfloat16_as_ushort(hx);
    unsigned lo = ((unsigned)__bfloat16_as_ushort(ly) << 16) | __bfloat16_as_ushort(lx);
    return make_uint2(hi, lo);
}
__device__ __forceinline__ void bsplit(float v, __nv_bfloat16& h, __nv_bfloat16& l) {
    h = __float2bfloat16_rn(v);
    l = __float2bfloat16_rn(v - __bfloat162float(h));
}

#define MMA_BF16(d, a, b) \
    asm volatile("mma.sync.aligned.m16n8k16.row.col.f32.bf16.bf16.f32 " \
        "{%0,%1,%2,%3},{%4,%5,%6,%7},{%8,%9},{%0,%1,%2,%3};\n" \
        : "+f"(d[0]), "+f"(d[1]), "+f"(d[2]), "+f"(d[3]) \
        : "r"(a[0]), "r"(a[1]), "r"(a[2]), "r"(a[3]), "r"(b[0]), "r"(b[1]))

// ---------------- K0: build P, pack P to bf16 hi/lo, zero stats ----------------
__global__ void k_prep(const int* __restrict__ el) {
    __shared__ float deg[NNODE];
    __shared__ float dinv[NNODE];
    __shared__ float Ps[NNODE * NNODE];
    int t = threadIdx.x;
    if (t < NNODE) deg[t] = 0.f;
    for (int i = t; i < NNODE * NNODE; i += 256) Ps[i] = 0.f;
    __syncthreads();
    for (int i = t; i < NEDGE + NNODE; i += 256) {
        int d = (i < NEDGE) ? el[NEDGE + i] : (i - NEDGE);
        atomicAdd(&deg[d], 1.f);
    }
    __syncthreads();
    if (t < NNODE) dinv[t] = (deg[t] > 0.f) ? rsqrtf(deg[t]) : 0.f;
    __syncthreads();
    for (int i = t; i < NEDGE + NNODE; i += 256) {
        int s = (i < NEDGE) ? el[i] : (i - NEDGE);
        int d = (i < NEDGE) ? el[NEDGE + i] : (i - NEDGE);
        atomicAdd(&Ps[d * NNODE + s], dinv[s] * dinv[d]);
    }
    __syncthreads();
    for (int i = t; i < NNODE * NNODE; i += 256) g_P[i] = Ps[i];
    for (int i = t; i < 64 * 32; i += 256) {
        int d = i >> 5, sp = i & 31;
        uint2 s = split2(Ps[d * 64 + 2 * sp], Ps[d * 64 + 2 * sp + 1]);
        g_Ph[i] = s.x; g_Pl[i] = s.y;
    }
    if (t < NNODE) { g_sum1[t] = 0.f; g_ssq1[t] = 0.f; g_sum2[t] = 0.f; g_ssq2[t] = 0.f; }
}

// ---------------- pack kernels ----------------
__global__ void k_pack_a(const float* __restrict__ xf) {
    int idx = blockIdx.x * 256 + threadIdx.x;
    int row = idx >> 10, kc = idx & 1023;
    float2 v = *reinterpret_cast<const float2*>(&xf[(size_t)row * DFP + kc * 2]);
    uint2 s = split2(v.x, v.y);
    g_Ah[idx] = s.x; g_Al[idx] = s.y;
}
__global__ void k_pack_b(const float* __restrict__ Wl1) {
    int idx = blockIdx.x * 256 + threadIdx.x;
    int n = idx >> 10, kc = idx & 1023;
    float2 v = make_float2(0.f, 0.f);
    if (n < H1D) v = *reinterpret_cast<const float2*>(&Wl1[(size_t)n * DFP + kc * 2]);
    uint2 s = split2(v.x, v.y);
    g_Bh[idx] = s.x; g_Bl[idx] = s.y;
}
__global__ void k_pack_w1(const float* __restrict__ W1) {
    int idx = blockIdx.x * 256 + threadIdx.x;     // 2560
    if (idx >= 64 * 40) return;
    int n = idx / 40, kp = idx % 40;
    int k0 = 2 * kp;
    float v0 = (k0 < FIN) ? W1[n * FIN + k0] : 0.f;
    float v1 = (k0 + 1 < FIN) ? W1[n * FIN + k0 + 1] : 0.f;
    uint2 s = split2(v0, v1);
    g_W1h[idx] = s.x; g_W1l[idx] = s.y;
}
__global__ void k_pack_w2(const float* __restrict__ W2) {
    int idx = blockIdx.x * 256 + threadIdx.x;     // 1024
    if (idx >= 32 * 32) return;
    int n = idx >> 5, kp = idx & 31;
    uint2 s = split2(W2[n * 64 + 2 * kp], W2[n * 64 + 2 * kp + 1]);
    g_W2h[idx] = s.x; g_W2l[idx] = s.y;
}

// ---------------- fused GCN1 (tensor core): G1[b] = P @ (X[b]@W1^T) + b1, + stats ----
// smem u32 layout: Xh[64*44] | Xl | Bh[64*44] (W1 then P) | Bl | Yth(u16 64*72) | Ytl
__global__ __launch_bounds__(128)
void k_fg1(const float* __restrict__ xn, const float* __restrict__ b1) {
    extern __shared__ unsigned sm[];
    unsigned* Xh = sm;
    unsigned* Xl = sm + 2816;
    unsigned* Bh = sm + 5632;
    unsigned* Bl = sm + 8448;
    __nv_bfloat16* Yth = (__nv_bfloat16*)(sm + 11264);
    __nv_bfloat16* Ytl = (__nv_bfloat16*)(sm + 13568);

    int b = blockIdx.x, t = threadIdx.x;
    int wid = t >> 5, lane = t & 31, g = lane >> 2, c = lane & 3;
    int r = wid * 16 + g;

    const float* Xb = xn + (size_t)b * (NNODE * FIN);
    for (int i = t; i < 64 * 40; i += 128) {
        int rr = i / 40, kp = i - rr * 40;
        int k0 = 2 * kp;
        float v0 = (k0 < FIN) ? Xb[rr * FIN + k0] : 0.f;
        float v1 = (k0 + 1 < FIN) ? Xb[rr * FIN + k0 + 1] : 0.f;
        uint2 s = split2(v0, v1);
        Xh[rr * 44 + kp] = s.x; Xl[rr * 44 + kp] = s.y;
        Bh[rr * 44 + kp] = g_W1h[i]; Bl[rr * 44 + kp] = g_W1l[i];
    }
    __syncthreads();

    // phase 1: Y = X @ W1^T  (M=64, N=64, K=80)
    float acc[8][4] = {};
    #pragma unroll
    for (int kc = 0; kc < 5; kc++) {
        int ko = kc * 8;
        unsigned ah[4], al[4];
        ah[0] = Xh[r * 44 + c + ko];       ah[1] = Xh[(r + 8) * 44 + c + ko];
        ah[2] = Xh[r * 44 + c + 4 + ko];   ah[3] = Xh[(r + 8) * 44 + c + 4 + ko];
        al[0] = Xl[r * 44 + c + ko];       al[1] = Xl[(r + 8) * 44 + c + ko];
        al[2] = Xl[r * 44 + c + 4 + ko];   al[3] = Xl[(r + 8) * 44 + c + 4 + ko];
        #pragma unroll
        for (int ni = 0; ni < 8; ni++) {
            int n = ni * 8 + g;
            unsigned bh[2] = { Bh[n * 44 + c + ko], Bh[n * 44 + c + 4 + ko] };
            unsigned bl[2] = { Bl[n * 44 + c + ko], Bl[n * 44 + c + 4 + ko] };
            MMA_BF16(acc[ni], ah, bh);
            MMA_BF16(acc[ni], ah, bl);
            MMA_BF16(acc[ni], al, bh);
        }
    }

    // store Y transposed (bf16 split): Yt[o][s]
    #pragma unroll
    for (int ni = 0; ni < 8; ni++) {
        int cn = ni * 8 + 2 * c;
        __nv_bfloat16 h, l;
        bsplit(acc[ni][0], h, l); Yth[cn * 72 + r] = h;           Ytl[cn * 72 + r] = l;
        bsplit(acc[ni][1], h, l); Yth[(cn + 1) * 72 + r] = h;     Ytl[(cn + 1) * 72 + r] = l;
        bsplit(acc[ni][2], h, l); Yth[cn * 72 + r + 8] = h;       Ytl[cn * 72 + r + 8] = l;
        bsplit(acc[ni][3], h, l); Yth[(cn + 1) * 72 + r + 8] = h; Ytl[(cn + 1) * 72 + r + 8] = l;
    }
    __syncthreads();
    // load P into B buffers (stride 36)
    for (int i = t; i < 64 * 32; i += 128) {
        int d = i >> 5, sp = i & 31;
        Bh[d * 36 + sp] = g_Ph[i]; Bl[d * 36 + sp] = g_Pl[i];
    }
    __syncthreads();

    // phase 2: G1 = P @ Y + b1  (M=64 d, N=64 o, K=64 s)
    float ac2[8][4] = {};
    #pragma unroll
    for (int kc = 0; kc < 4; kc++) {
        int ko = kc * 8;
        unsigned ah[4], al[4];
        ah[0] = Bh[r * 36 + c + ko];       ah[1] = Bh[(r + 8) * 36 + c + ko];
        ah[2] = Bh[r * 36 + c + 4 + ko];   ah[3] = Bh[(r + 8) * 36 + c + 4 + ko];
        al[0] = Bl[r * 36 + c + ko];       al[1] = Bl[(r + 8) * 36 + c + ko];
        al[2] = Bl[r * 36 + c + 4 + ko];   al[3] = Bl[(r + 8) * 36 + c + 4 + ko];
        #pragma unroll
        for (int ni = 0; ni < 8; ni++) {
            int n = ni * 8 + g;
            unsigned bh[2], bl[2];
            bh[0] = *reinterpret_cast<const unsigned*>(&Yth[n * 72 + 2 * c + kc * 16]);
            bh[1] = *reinterpret_cast<const unsigned*>(&Yth[n * 72 + 2 * c + 8 + kc * 16]);
            bl[0] = *reinterpret_cast<const unsigned*>(&Ytl[n * 72 + 2 * c + kc * 16]);
            bl[1] = *reinterpret_cast<const unsigned*>(&Ytl[n * 72 + 2 * c + 8 + kc * 16]);
            MMA_BF16(ac2[ni], ah, bh);
            MMA_BF16(ac2[ni], ah, bl);
            MMA_BF16(ac2[ni], al, bh);
        }
    }

    // epilogue: + b1, write G1, BN1 stats
    float* out = g_G1 + (size_t)b * (NNODE * C1);
    float s0 = 0.f, q0 = 0.f, s1 = 0.f, q1 = 0.f;
    #pragma unroll
    for (int ni = 0; ni < 8; ni++) {
        int cn = ni * 8 + 2 * c;
        float bv0 = __ldg(&b1[cn]), bv1 = __ldg(&b1[cn + 1]);
        float v00 = ac2[ni][0] + bv0, v01 = ac2[ni][1] + bv1;
        float v10 = ac2[ni][2] + bv0, v11 = ac2[ni][3] + bv1;
        *reinterpret_cast<float2*>(&out[r * 64 + cn]) = make_float2(v00, v01);
        *reinterpret_cast<float2*>(&out[(r + 8) * 64 + cn]) = make_float2(v10, v11);
        s0 += v00 + v01; q0 += fmaf(v00, v00, v01 * v01);
        s1 += v10 + v11; q1 += fmaf(v10, v10, v11 * v11);
    }
    s0 += __shfl_xor_sync(0xffffffffu, s0, 1); s0 += __shfl_xor_sync(0xffffffffu, s0, 2);
    q0 += __shfl_xor_sync(0xffffffffu, q0, 1); q0 += __shfl_xor_sync(0xffffffffu, q0, 2);
    s1 += __shfl_xor_sync(0xffffffffu, s1, 1); s1 += __shfl_xor_sync(0xffffffffu, s1, 2);
    q1 += __shfl_xor_sync(0xffffffffu, q1, 1); q1 += __shfl_xor_sync(0xffffffffu, q1, 2);
    if (c == 0) {
        atomicAdd(&g_sum1[r], s0);     atomicAdd(&g_ssq1[r], q0);
        atomicAdd(&g_sum1[r + 8], s1); atomicAdd(&g_ssq1[r + 8], q1);
    }
}

// ---------------- fused GCN2 (tensor core): G2[b] = P @ (relu(bn1(G1[b]))@W2^T) + b2 --
// smem u32: Ah[2304] | Al | Ph[2304] | Pl | W2h[1152] | W2l | Zth(u16 32*72) | Ztl
__global__ __launch_bounds__(128)
void k_fg2(const float* __restrict__ g1, const float* __restrict__ be1,
           const float* __restrict__ b2) {
    extern __shared__ unsigned sm[];
    unsigned* Ah = sm;
    unsigned* Al = sm + 2304;
    unsigned* Ph = sm + 4608;
    unsigned* Pl = sm + 6912;
    unsigned* W2h = sm + 9216;
    unsigned* W2l = sm + 10368;
    __nv_bfloat16* Zth = (__nv_bfloat16*)(sm + 11520);
    __nv_bfloat16* Ztl = (__nv_bfloat16*)(sm + 12672);
    __shared__ float a1s[64], c1s[64];

    int b = blockIdx.x, t = threadIdx.x;
    int wid = t >> 5, lane = t & 31, g = lane >> 2, c = lane & 3;
    int r = wid * 16 + g;

    if (t < 64) {
        const float invn = 1.0f / (float)(B_ * C1);
        float m = g_sum1[t] * invn;
        float v = g_ssq1[t] * invn - m * m;
        float aa = g1[t] * rsqrtf(v + 1e-5f);
        a1s[t] = aa;
        c1s[t] = be1[t] - m * aa;
    }
    for (int i = t; i < 64 * 32; i += 128) {
        int d = i >> 5, sp = i & 31;
        Ph[d * 36 + sp] = g_Ph[i]; Pl[d * 36 + sp] = g_Pl[i];
    }
    for (int i = t; i < 32 * 32; i += 128) {
        int n = i >> 5, kp = i & 31;
        W2h[n * 36 + kp] = g_W2h[i]; W2l[n * 36 + kp] = g_W2l[i];
    }
    __syncthreads();

    const float* Gb = g_G1 + (size_t)b * (NNODE * C1);
    for (int i = t; i < 64 * 32; i += 128) {
        int rr = i >> 5, kp = i & 31;
        float aa = a1s[rr], cc = c1s[rr];
        float v0 = fmaxf(fmaf(Gb[rr * 64 + 2 * kp], aa, cc), 0.f);
        float v1 = fmaxf(fmaf(Gb[rr * 64 + 2 * kp + 1], aa, cc), 0.f);
        uint2 s = split2(v0, v1);
        Ah[rr * 36 + kp] = s.x; Al[rr * 36 + kp] = s.y;
    }
    __syncthreads();

    // phase 1: Z = relu(bn(G1)) @ W2^T  (M=64 d, N=32 j, K=64)
    float acc[4][4] = {};
    #pragma unroll
    for (int kc = 0; kc < 4; kc++) {
        int ko = kc * 8;
        unsigned ah[4], al[4];
        ah[0] = Ah[r * 36 + c + ko];       ah[1] = Ah[(r + 8) * 36 + c + ko];
        ah[2] = Ah[r * 36 + c + 4 + ko];   ah[3] = Ah[(r + 8) * 36 + c + 4 + ko];
        al[0] = Al[r * 36 + c + ko];       al[1] = Al[(r + 8) * 36 + c + ko];
        al[2] = Al[r * 36 + c + 4 + ko];   al[3] = Al[(r + 8) * 36 + c + 4 + ko];
        #pragma unroll
        for (int ni = 0; ni < 4; ni++) {
            int n = ni * 8 + g;
            unsigned bh[2] = { W2h[n * 36 + c + ko], W2h[n * 36 + c + 4 + ko] };
            unsigned bl[2] = { W2l[n * 36 + c + ko], W2l[n * 36 + c + 4 + ko] };
            MMA_BF16(acc[ni], ah, bh);
            MMA_BF16(acc[ni], ah, bl);
            MMA_BF16(acc[ni], al, bh);
        }
    }

    // store Z transposed (bf16 split): Zt[j][s]
    #pragma unroll
    for (int ni = 0; ni < 4; ni++) {
        int cn = ni * 8 + 2 * c;
        __nv_bfloat16 h, l;
        bsplit(acc[ni][0], h, l); Zth[cn * 72 + r] = h;           Ztl[cn * 72 + r] = l;
        bsplit(acc[ni][1], h, l); Zth[(cn + 1) * 72 + r] = h;     Ztl[(cn + 1) * 72 + r] = l;
        bsplit(acc[ni][2], h, l); Zth[cn * 72 + r + 8] = h;       Ztl[cn * 72 + r + 8] = l;
        bsplit(acc[ni][3], h, l); Zth[(cn + 1) * 72 + r + 8] = h; Ztl[(cn + 1) * 72 + r + 8] = l;
    }
    __syncthreads();

    // phase 2: G2 = P @ Z + b2  (M=64 d, N=32 j, K=64 s)
    float ac2[4][4] = {};
    #pragma unroll
    for (int kc = 0; kc < 4; kc++) {
        int ko = kc * 8;
        unsigned ah[4], al[4];
        ah[0] = Ph[r * 36 + c + ko];       ah[1] = Ph[(r + 8) * 36 + c + ko];
        ah[2] = Ph[r * 36 + c + 4 + ko];   ah[3] = Ph[(r + 8) * 36 + c + 4 + ko];
        al[0] = Pl[r * 36 + c + ko];       al[1] = Pl[(r + 8) * 36 + c + ko];
        al[2] = Pl[r * 36 + c + 4 + ko];   al[3] = Pl[(r + 8) * 36 + c + 4 + ko];
        #pragma unroll
        for (int ni = 0; ni < 4; ni++) {
            int n = ni * 8 + g;
            unsigned bh[2], bl[2];
            bh[0] = *reinterpret_cast<const unsigned*>(&Zth[n * 72 + 2 * c + kc * 16]);
            bh[1] = *reinterpret_cast<const unsigned*>(&Zth[n * 72 + 2 * c + 8 + kc * 16]);
            bl[0] = *reinterpret_cast<const unsigned*>(&Ztl[n * 72 + 2 * c + kc * 16]);
            bl[1] = *reinterpret_cast<const unsigned*>(&Ztl[n * 72 + 2 * c + 8 + kc * 16]);
            MMA_BF16(ac2[ni], ah, bh);
            MMA_BF16(ac2[ni], ah, bl);
            MMA_BF16(ac2[ni], al, bh);
        }
    }

    // epilogue: + b2, write G2, BN2 stats
    float* out = g_G2 + (size_t)b * (NNODE * C2);
    float s0 = 0.f, q0 = 0.f, s1 = 0.f, q1 = 0.f;
    #pragma unroll
    for (int ni = 0; ni < 4; ni++) {
        int cn = ni * 8 + 2 * c;
        float bv0 = __ldg(&b2[cn]), bv1 = __ldg(&b2[cn + 1]);
        float v00 = ac2[ni][0] + bv0, v01 = ac2[ni][1] + bv1;
        float v10 = ac2[ni][2] + bv0, v11 = ac2[ni][3] + bv1;
        *reinterpret_cast<float2*>(&out[r * 32 + cn]) = make_float2(v00, v01);
        *reinterpret_cast<float2*>(&out[(r + 8) * 32 + cn]) = make_float2(v10, v11);
        s0 += v00 + v01; q0 += fmaf(v00, v00, v01 * v01);
        s1 += v10 + v11; q1 += fmaf(v10, v10, v11 * v11);
    }
    s0 += __shfl_xor_sync(0xffffffffu, s0, 1); s0 += __shfl_xor_sync(0xffffffffu, s0, 2);
    q0 += __shfl_xor_sync(0xffffffffu, q0, 1); q0 += __shfl_xor_sync(0xffffffffu, q0, 2);
    s1 += __shfl_xor_sync(0xffffffffu, s1, 1); s1 += __shfl_xor_sync(0xffffffffu, s1, 2);
    q1 += __shfl_xor_sync(0xffffffffu, q1, 1); q1 += __shfl_xor_sync(0xffffffffu, q1, 2);
    if (c == 0) {
        atomicAdd(&g_sum2[r], s0);     atomicAdd(&g_ssq2[r], q0);
        atomicAdd(&g_sum2[r + 8], s1); atomicAdd(&g_ssq2[r + 8], q1);
    }
}

// ---------------- K5: bn2 (inline coeffs) + relu + max-pool over nodes ---------------
__global__ void k_pool(const float* __restrict__ g2, const float* __restrict__ be2) {
    __shared__ float a2s[64], c2s[64];
    int t = threadIdx.x;
    if (t < 64) {
        const float invn = 1.0f / (float)(B_ * C2);
        float m = g_sum2[t] * invn;
        float v = g_ssq2[t] * invn - m * m;
        float aa = g2[t] * rsqrtf(v + 1e-5f);
        a2s[t] = aa;
        c2s[t] = be2[t] - m * aa;
    }
    __syncthreads();
    int bl = t >> 5, j = t & 31;
    int b = blockIdx.x * 8 + bl;
    const float* src = g_G2 + (size_t)b * 2048 + j;
    float m = 0.f;
    #pragma unroll 8
    for (int d = 0; d < 64; d++) {
        float v = fmaxf(fmaf(src[d * 32], a2s[d], c2s[d]), 0.f);
        m = fmaxf(m, v);
    }
    g_pool[b * 32 + j] = m;
}

// ---------------- MLP1 tensor-core: H1 = relu(xf @ Wl1^T + bl1), bf16 split ----------
__global__ __launch_bounds__(256, 2)
void k_mlp1_tc(const float* __restrict__ bias) {
    __shared__ unsigned Ah[128 * 20], Al[128 * 20];
    __shared__ unsigned Bh[64 * 20],  Bl[64 * 20];
    int t = threadIdx.x;
    int m0 = blockIdx.x * 128, n0 = blockIdx.y * 64;
    int wid = t >> 5, lane = t & 31;
    int wm = (wid & 3) * 32, wn = (wid >> 2) * 32;
    int g = lane >> 2, c = lane & 3;
    int arow = t >> 2, ac4 = (t & 3) * 4;

    float acc[2][4][4] = {};

    for (int ch = 0; ch < 64; ch++) {
        __syncthreads();
        int kbase = ch * 16;
        #pragma unroll
        for (int rep = 0; rep < 2; rep++) {
            int row = arow + rep * 64;
            size_t gi = (size_t)(m0 + row) * 1024 + kbase + ac4;
            *reinterpret_cast<uint4*>(&Ah[row * 20 + ac4]) =
                *reinterpret_cast<const uint4*>(&g_Ah[gi]);
            *reinterpret_cast<uint4*>(&Al[row * 20 + ac4]) =
                *reinterpret_cast<const uint4*>(&g_Al[gi]);
        }
        {
            size_t gi = (size_t)(n0 + arow) * 1024 + kbase + ac4;
            *reinterpret_cast<uint4*>(&Bh[arow * 20 + ac4]) =
                *reinterpret_cast<const uint4*>(&g_Bh[gi]);
            *reinterpret_cast<uint4*>(&Bl[arow * 20 + ac4]) =
                *reinterpret_cast<const uint4*>(&g_Bl[gi]);
        }
        __syncthreads();
        #pragma unroll
        for (int kk = 0; kk < 2; kk++) {
            int ko = kk * 8;
            unsigned ah[2][4], al[2][4], bh[4][2], bl[4][2];
            #pragma unroll
            for (int mi = 0; mi < 2; mi++) {
                int r = wm + mi * 16 + g;
                ah[mi][0] = Ah[r * 20 + c + ko];
                ah[mi][1] = Ah[(r + 8) * 20 + c + ko];
                ah[mi][2] = Ah[r * 20 + c + 4 + ko];
                ah[mi][3] = Ah[(r + 8) * 20 + c + 4 + ko];
                al[mi][0] = Al[r * 20 + c + ko];
                al[mi][1] = Al[(r + 8) * 20 + c + ko];
                al[mi][2] = Al[r * 20 + c + 4 + ko];
                al[mi][3] = Al[(r + 8) * 20 + c + 4 + ko];
            }
            #pragma unroll
            for (int ni = 0; ni < 4; ni++) {
                int n = wn + ni * 8 + g;
                bh[ni][0] = Bh[n * 20 + c + ko];
                bh[ni][1] = Bh[n * 20 + c + 4 + ko];
                bl[ni][0] = Bl[n * 20 + c + ko];
                bl[ni][1] = Bl[n * 20 + c + 4 + ko];
            }
            #pragma unroll
            for (int mi = 0; mi < 2; mi++) {
                #pragma unroll
                for (int ni = 0; ni < 4; ni++) {
                    MMA_BF16(acc[mi][ni], ah[mi], bh[ni]);
                    MMA_BF16(acc[mi][ni], ah[mi], bl[ni]);
                    MMA_BF16(acc[mi][ni], al[mi], bh[ni]);
                }
            }
        }
    }

    #pragma unroll
    for (int mi = 0; mi < 2; mi++) {
        #pragma unroll
        for (int ni = 0; ni < 4; ni++) {
            int col = n0 + wn + ni * 8 + 2 * c;
            if (col < H1D) {
                float bv0 = __ldg(&bias[col]), bv1 = __ldg(&bias[col + 1]);
                int r0 = m0 + wm + mi * 16 + g;
                float* p0 = g_H1 + (size_t)r0 * H1D + col;
                float* p1 = g_H1 + (size_t)(r0 + 8) * H1D + col;
                p0[0] = fmaxf(acc[mi][ni][0] + bv0, 0.f);
                p0[1] = fmaxf(acc[mi][ni][1] + bv1, 0.f);
                p1[0] = fmaxf(acc[mi][ni][2] + bv0, 0.f);
                p1[1] = fmaxf(acc[mi][ni][3] + bv1, 0.f);
            }
        }
    }
}

// ---------------- MLP2 (scalar 64x64): H2 = relu(H1 @ Wl2^T + bl2) ----------------
__global__ void k_mlp2(const float* __restrict__ Bw, const float* __restrict__ bias) {
    __shared__ __align__(16) float As[16 * 68];
    __shared__ __align__(16) float Bs[16 * 68];
    const float* A = g_H1;
    float* C = g_H2;
    int m0 = blockIdx.x * 64;
    int t = threadIdx.x;
    int tm = (t >> 4) * 4, tn = (t & 15) * 4;
    float acc[4][4] = {};
    for (int k0 = 0; k0 < H1D; k0 += 16) {
        for (int i = t; i < 1024; i += 256) {
            int r = i >> 4, kk = i & 15;
            As[kk * 68 + r] = A[(size_t)(m0 + r) * H1D + k0 + kk];
            Bs[kk * 68 + r] = Bw[(size_t)r * H1D + k0 + kk];
        }
        __syncthreads();
        #pragma unroll
        for (int kk = 0; kk < 16; kk++) {
            float4 a = *reinterpret_cast<const float4*>(&As[kk * 68 + tm]);
            float4 b = *reinterpret_cast<const float4*>(&Bs[kk * 68 + tn]);
            acc[0][0] = fmaf(a.x, b.x, acc[0][0]); acc[0][1] = fmaf(a.x, b.y, acc[0][1]);
            acc[0][2] = fmaf(a.x, b.z, acc[0][2]); acc[0][3] = fmaf(a.x, b.w, acc[0][3]);
            acc[1][0] = fmaf(a.y, b.x, acc[1][0]); acc[1][1] = fmaf(a.y, b.y, acc[1][1]);
            acc[1][2] = fmaf(a.y, b.z, acc[1][2]); acc[1][3] = fmaf(a.y, b.w, acc[1][3]);
            acc[2][0] = fmaf(a.z, b.x, acc[2][0]); acc[2][1] = fmaf(a.z, b.y, acc[2][1]);
            acc[2][2] = fmaf(a.z, b.z, acc[2][2]); acc[2][3] = fmaf(a.z, b.w, acc[2][3]);
            acc[3][0] = fmaf(a.w, b.x, acc[3][0]); acc[3][1] = fmaf(a.w, b.y, acc[3][1]);
            acc[3][2] = fmaf(a.w, b.z, acc[3][2]); acc[3][3] = fmaf(a.w, b.w, acc[3][3]);
        }
        __syncthreads();
    }
    #pragma unroll
    for (int i = 0; i < 4; i++) {
        int row = m0 + tm + i;
        #pragma unroll
        for (int j = 0; j < 4; j++) {
            int col = tn + j;
            C[(size_t)row * H2D + col] = fmaxf(acc[i][j] + __ldg(&bias[col]), 0.f);
        }
    }
}

// ---------------- final: out = [pool, H2] @ Wfc^T + bfc ----------------
__global__ void k_final(const float* __restrict__ Wfc, const float* __restrict__ bfc,
                        float* __restrict__ out) {
    __shared__ float Ws[192];
    int t = threadIdx.x;
    if (t < 192) Ws[t] = Wfc[t];
    __syncthreads();
    int b = blockIdx.x * 256 + t;
    float a0 = __ldg(&bfc[0]), a1 = __ldg(&bfc[1]);
    const float* pp = g_pool + b * 32;
    const float* hh = g_H2 + b * 64;
    #pragma unroll
    for (int j = 0; j < 32; j++) {
        float v = pp[j];
        a0 = fmaf(v, Ws[j], a0);
        a1 = fmaf(v, Ws[96 + j], a1);
    }
    #pragma unroll
    for (int j = 0; j < 64; j++) {
        float v = hh[j];
        a0 = fmaf(v, Ws[32 + j], a0);
        a1 = fmaf(v, Ws[128 + j], a1);
    }
    out[b * 2]     = a0;
    out[b * 2 + 1] = a1;
}

// ---------------- launch ----------------
extern "C" void kernel_launch(void* const* d_in, const int* in_sizes, int n_in,
                              void* d_out, int out_size) {
    const float* xf  = (const float*)d_in[0];
    const float* xn  = (const float*)d_in[1];
    const int*   el  = (const int*)  d_in[2];
    const float* W1  = (const float*)d_in[3];
    const float* b1  = (const float*)d_in[4];
    const float* g1  = (const float*)d_in[5];
    const float* be1 = (const float*)d_in[6];
    const float* W2  = (const float*)d_in[7];
    const float* b2  = (const float*)d_in[8];
    const float* g2  = (const float*)d_in[9];
    const float* be2 = (const float*)d_in[10];
    const float* Wl1 = (const float*)d_in[11];
    const float* bl1 = (const float*)d_in[12];
    const float* Wl2 = (const float*)d_in[13];
    const float* bl2 = (const float*)d_in[14];
    const float* Wfc = (const float*)d_in[15];
    const float* bfc = (const float*)d_in[16];
    float* out = (float*)d_out;

    const int SMEM_FG1 = 15872 * 4;   // 63488 B
    const int SMEM_FG2 = 13824 * 4;   // 55296 B
    cudaFuncSetAttribute(k_fg1, cudaFuncAttributeMaxDynamicSharedMemorySize, SMEM_FG1);
    cudaFuncSetAttribute(k_fg2, cudaFuncAttributeMaxDynamicSharedMemorySize, SMEM_FG2);

    k_prep<<<1, 256>>>(el);
    k_pack_w1<<<10, 256>>>(W1);
    k_pack_w2<<<4, 256>>>(W2);
    k_pack_b<<<(H1PAD * (DFP / 2)) / 256, 256>>>(Wl1);
    k_pack_a<<<(B_ * (DFP / 2)) / 256, 256>>>(xf);

    // graph path: fused tensor-core GCN layers
    k_fg1<<<B_, 128, SMEM_FG1>>>(xn, b1);
    k_fg2<<<B_, 128, SMEM_FG2>>>(g1, be1, b2);
    k_pool<<<B_ / 8, 256>>>(g2, be2);

    // fingerprint MLP path
    k_mlp1_tc<<<dim3(B_ / 128, H1PAD / 64), 256>>>(bl1);
    k_mlp2<<<B_ / 64, 256>>>(Wl2, bl2);

    k_final<<<B_ / 256, 256>>>(Wfc, bfc, out);
}

// round 15
// speedup vs baseline: 1.4868x; 1.0443x over previous
#include <cuda_runtime.h>
#include <cuda_bf16.h>

#define B_    4096
#define NNODE 64
#define FIN   67
#define C1    64
#define C2    32
#define DFP   2048
#define H1D   400
#define H1PAD 448
#define H2D   64
#define NEDGE 512

// ---------------- scratch (device globals; no allocations allowed) ----------------
__device__ float g_P [NNODE * NNODE];
__device__ float g_G1[B_ * NNODE * C1];
__device__ float g_G2[B_ * NNODE * C2];
__device__ float g_pool[B_ * C2];
__device__ float g_H1[B_ * H1D];
__device__ float g_H2[B_ * H2D];
__device__ float g_sum1[NNODE], g_ssq1[NNODE], g_sum2[NNODE], g_ssq2[NNODE];
// bf16-split packed operands (u32 = 2 bf16 along k)
__device__ unsigned g_Ah[B_ * (DFP / 2)];
__device__ unsigned g_Al[B_ * (DFP / 2)];
__device__ unsigned g_Bh[H1PAD * (DFP / 2)];
__device__ unsigned g_Bl[H1PAD * (DFP / 2)];
__device__ unsigned g_W1h[64 * 40], g_W1l[64 * 40];   // W1 [64][K80 pad] packed
__device__ unsigned g_Ph [64 * 32], g_Pl [64 * 32];   // P  [64][K64]     packed
__device__ unsigned g_W2h[32 * 32], g_W2l[32 * 32];   // W2 [32][K64]     packed

// ---------------- helpers ----------------
__device__ __forceinline__ uint2 split2(float x, float y) {
    __nv_bfloat16 hx = __float2bfloat16_rn(x), hy = __float2bfloat16_rn(y);
    float rx = x - __bfloat162float(hx), ry = y - __bfloat162float(hy);
    __nv_bfloat16 lx = __float2bfloat16_rn(rx), ly = __float2bfloat16_rn(ry);
    unsigned hi = ((unsigned)__bfloat16_as_ushort(hy) << 16) | __bfloat16_as_ushort(hx);
    unsigned lo = ((unsigned)__bfloat16_as_ushort(ly) << 16) | __bfloat16_as_ushort(lx);
    return make_uint2(hi, lo);
}
__device__ __forceinline__ void bsplit(float v, __nv_bfloat16& h, __nv_bfloat16& l) {
    h = __float2bfloat16_rn(v);
    l = __float2bfloat16_rn(v - __bfloat162float(h));
}
__device__ __forceinline__ void cpa16(unsigned saddr, const void* g) {
    asm volatile("cp.async.cg.shared.global [%0], [%1], 16;" :: "r"(saddr), "l"(g));
}

#define MMA_BF16(d, a, b) \
    asm volatile("mma.sync.aligned.m16n8k16.row.col.f32.bf16.bf16.f32 " \
        "{%0,%1,%2,%3},{%4,%5,%6,%7},{%8,%9},{%0,%1,%2,%3};\n" \
        : "+f"(d[0]), "+f"(d[1]), "+f"(d[2]), "+f"(d[3]) \
        : "r"(a[0]), "r"(a[1]), "r"(a[2]), "r"(a[3]), "r"(b[0]), "r"(b[1]))

// ---------------- K0: build P, pack P/W1/W2 to bf16 hi/lo, zero stats ----------------
__global__ void k_prep(const int* __restrict__ el, const float* __restrict__ W1,
                       const float* __restrict__ W2) {
    __shared__ float deg[NNODE];
    __shared__ float dinv[NNODE];
    __shared__ float Ps[NNODE * NNODE];
    int t = threadIdx.x;
    // pack W1 / W2 (independent of P)
    for (int i = t; i < 64 * 40; i += 256) {
        int n = i / 40, kp = i - n * 40;
        int k0 = 2 * kp;
        float v0 = (k0 < FIN) ? W1[n * FIN + k0] : 0.f;
        float v1 = (k0 + 1 < FIN) ? W1[n * FIN + k0 + 1] : 0.f;
        uint2 s = split2(v0, v1);
        g_W1h[i] = s.x; g_W1l[i] = s.y;
    }
    for (int i = t; i < 32 * 32; i += 256) {
        int n = i >> 5, kp = i & 31;
        uint2 s = split2(W2[n * 64 + 2 * kp], W2[n * 64 + 2 * kp + 1]);
        g_W2h[i] = s.x; g_W2l[i] = s.y;
    }
    if (t < NNODE) deg[t] = 0.f;
    for (int i = t; i < NNODE * NNODE; i += 256) Ps[i] = 0.f;
    __syncthreads();
    for (int i = t; i < NEDGE + NNODE; i += 256) {
        int d = (i < NEDGE) ? el[NEDGE + i] : (i - NEDGE);
        atomicAdd(&deg[d], 1.f);
    }
    __syncthreads();
    if (t < NNODE) dinv[t] = (deg[t] > 0.f) ? rsqrtf(deg[t]) : 0.f;
    __syncthreads();
    for (int i = t; i < NEDGE + NNODE; i += 256) {
        int s = (i < NEDGE) ? el[i] : (i - NEDGE);
        int d = (i < NEDGE) ? el[NEDGE + i] : (i - NEDGE);
        atomicAdd(&Ps[d * NNODE + s], dinv[s] * dinv[d]);
    }
    __syncthreads();
    for (int i = t; i < NNODE * NNODE; i += 256) g_P[i] = Ps[i];
    for (int i = t; i < 64 * 32; i += 256) {
        int d = i >> 5, sp = i & 31;
        uint2 s = split2(Ps[d * 64 + 2 * sp], Ps[d * 64 + 2 * sp + 1]);
        g_Ph[i] = s.x; g_Pl[i] = s.y;
    }
    if (t < NNODE) { g_sum1[t] = 0.f; g_ssq1[t] = 0.f; g_sum2[t] = 0.f; g_ssq2[t] = 0.f; }
}

// ---------------- pack kernels ----------------
__global__ void k_pack_a(const float* __restrict__ xf) {
    int idx = blockIdx.x * 256 + threadIdx.x;
    int row = idx >> 10, kc = idx & 1023;
    float2 v = *reinterpret_cast<const float2*>(&xf[(size_t)row * DFP + kc * 2]);
    uint2 s = split2(v.x, v.y);
    g_Ah[idx] = s.x; g_Al[idx] = s.y;
}
__global__ void k_pack_b(const float* __restrict__ Wl1) {
    int idx = blockIdx.x * 256 + threadIdx.x;
    int n = idx >> 10, kc = idx & 1023;
    float2 v = make_float2(0.f, 0.f);
    if (n < H1D) v = *reinterpret_cast<const float2*>(&Wl1[(size_t)n * DFP + kc * 2]);
    uint2 s = split2(v.x, v.y);
    g_Bh[idx] = s.x; g_Bl[idx] = s.y;
}

// ---------------- fused GCN1 (tensor core): G1[b] = P @ (X[b]@W1^T) + b1, + stats ----
// smem u32 layout: Xh[64*44] | Xl | Bh[64*44] (W1 then P) | Bl | Yth(u16 64*72) | Ytl
__global__ __launch_bounds__(128)
void k_fg1(const float* __restrict__ xn, const float* __restrict__ b1) {
    extern __shared__ unsigned sm[];
    unsigned* Xh = sm;
    unsigned* Xl = sm + 2816;
    unsigned* Bh = sm + 5632;
    unsigned* Bl = sm + 8448;
    __nv_bfloat16* Yth = (__nv_bfloat16*)(sm + 11264);
    __nv_bfloat16* Ytl = (__nv_bfloat16*)(sm + 13568);

    int b = blockIdx.x, t = threadIdx.x;
    int wid = t >> 5, lane = t & 31, g = lane >> 2, c = lane & 3;
    int r = wid * 16 + g;

    const float* Xb = xn + (size_t)b * (NNODE * FIN);
    for (int i = t; i < 64 * 40; i += 128) {
        int rr = i / 40, kp = i - rr * 40;
        int k0 = 2 * kp;
        float v0 = (k0 < FIN) ? Xb[rr * FIN + k0] : 0.f;
        float v1 = (k0 + 1 < FIN) ? Xb[rr * FIN + k0 + 1] : 0.f;
        uint2 s = split2(v0, v1);
        Xh[rr * 44 + kp] = s.x; Xl[rr * 44 + kp] = s.y;
        Bh[rr * 44 + kp] = g_W1h[i]; Bl[rr * 44 + kp] = g_W1l[i];
    }
    __syncthreads();

    // phase 1: Y = X @ W1^T  (M=64, N=64, K=80)
    float acc[8][4] = {};
    #pragma unroll
    for (int kc = 0; kc < 5; kc++) {
        int ko = kc * 8;
        unsigned ah[4], al[4];
        ah[0] = Xh[r * 44 + c + ko];       ah[1] = Xh[(r + 8) * 44 + c + ko];
        ah[2] = Xh[r * 44 + c + 4 + ko];   ah[3] = Xh[(r + 8) * 44 + c + 4 + ko];
        al[0] = Xl[r * 44 + c + ko];       al[1] = Xl[(r + 8) * 44 + c + ko];
        al[2] = Xl[r * 44 + c + 4 + ko];   al[3] = Xl[(r + 8) * 44 + c + 4 + ko];
        #pragma unroll
        for (int ni = 0; ni < 8; ni++) {
            int n = ni * 8 + g;
            unsigned bh[2] = { Bh[n * 44 + c + ko], Bh[n * 44 + c + 4 + ko] };
            unsigned bl[2] = { Bl[n * 44 + c + ko], Bl[n * 44 + c + 4 + ko] };
            MMA_BF16(acc[ni], ah, bh);
            MMA_BF16(acc[ni], ah, bl);
            MMA_BF16(acc[ni], al, bh);
        }
    }

    // store Y transposed (bf16 split): Yt[o][s]
    #pragma unroll
    for (int ni = 0; ni < 8; ni++) {
        int cn = ni * 8 + 2 * c;
        __nv_bfloat16 h, l;
        bsplit(acc[ni][0], h, l); Yth[cn * 72 + r] = h;           Ytl[cn * 72 + r] = l;
        bsplit(acc[ni][1], h, l); Yth[(cn + 1) * 72 + r] = h;     Ytl[(cn + 1) * 72 + r] = l;
        bsplit(acc[ni][2], h, l); Yth[cn * 72 + r + 8] = h;       Ytl[cn * 72 + r + 8] = l;
        bsplit(acc[ni][3], h, l); Yth[(cn + 1) * 72 + r + 8] = h; Ytl[(cn + 1) * 72 + r + 8] = l;
    }
    __syncthreads();
    // load P into B buffers (stride 36)
    for (int i = t; i < 64 * 32; i += 128) {
        int d = i >> 5, sp = i & 31;
        Bh[d * 36 + sp] = g_Ph[i]; Bl[d * 36 + sp] = g_Pl[i];
    }
    __syncthreads();

    // phase 2: G1 = P @ Y + b1  (M=64 d, N=64 o, K=64 s)
    float ac2[8][4] = {};
    #pragma unroll
    for (int kc = 0; kc < 4; kc++) {
        int ko = kc * 8;
        unsigned ah[4], al[4];
        ah[0] = Bh[r * 36 + c + ko];       ah[1] = Bh[(r + 8) * 36 + c + ko];
        ah[2] = Bh[r * 36 + c + 4 + ko];   ah[3] = Bh[(r + 8) * 36 + c + 4 + ko];
        al[0] = Bl[r * 36 + c + ko];       al[1] = Bl[(r + 8) * 36 + c + ko];
        al[2] = Bl[r * 36 + c + 4 + ko];   al[3] = Bl[(r + 8) * 36 + c + 4 + ko];
        #pragma unroll
        for (int ni = 0; ni < 8; ni++) {
            int n = ni * 8 + g;
            unsigned bh[2], bl[2];
            bh[0] = *reinterpret_cast<const unsigned*>(&Yth[n * 72 + 2 * c + kc * 16]);
            bh[1] = *reinterpret_cast<const unsigned*>(&Yth[n * 72 + 2 * c + 8 + kc * 16]);
            bl[0] = *reinterpret_cast<const unsigned*>(&Ytl[n * 72 + 2 * c + kc * 16]);
            bl[1] = *reinterpret_cast<const unsigned*>(&Ytl[n * 72 + 2 * c + 8 + kc * 16]);
            MMA_BF16(ac2[ni], ah, bh);
            MMA_BF16(ac2[ni], ah, bl);
            MMA_BF16(ac2[ni], al, bh);
        }
    }

    // epilogue: + b1, write G1, BN1 stats
    float* out = g_G1 + (size_t)b * (NNODE * C1);
    float s0 = 0.f, q0 = 0.f, s1 = 0.f, q1 = 0.f;
    #pragma unroll
    for (int ni = 0; ni < 8; ni++) {
        int cn = ni * 8 + 2 * c;
        float bv0 = __ldg(&b1[cn]), bv1 = __ldg(&b1[cn + 1]);
        float v00 = ac2[ni][0] + bv0, v01 = ac2[ni][1] + bv1;
        float v10 = ac2[ni][2] + bv0, v11 = ac2[ni][3] + bv1;
        *reinterpret_cast<float2*>(&out[r * 64 + cn]) = make_float2(v00, v01);
        *reinterpret_cast<float2*>(&out[(r + 8) * 64 + cn]) = make_float2(v10, v11);
        s0 += v00 + v01; q0 += fmaf(v00, v00, v01 * v01);
        s1 += v10 + v11; q1 += fmaf(v10, v10, v11 * v11);
    }
    s0 += __shfl_xor_sync(0xffffffffu, s0, 1); s0 += __shfl_xor_sync(0xffffffffu, s0, 2);
    q0 += __shfl_xor_sync(0xffffffffu, q0, 1); q0 += __shfl_xor_sync(0xffffffffu, q0, 2);
    s1 += __shfl_xor_sync(0xffffffffu, s1, 1); s1 += __shfl_xor_sync(0xffffffffu, s1, 2);
    q1 += __shfl_xor_sync(0xffffffffu, q1, 1); q1 += __shfl_xor_sync(0xffffffffu, q1, 2);
    if (c == 0) {
        atomicAdd(&g_sum1[r], s0);     atomicAdd(&g_ssq1[r], q0);
        atomicAdd(&g_sum1[r + 8], s1); atomicAdd(&g_ssq1[r + 8], q1);
    }
}

// ---------------- fused GCN2 (tensor core): G2[b] = P @ (relu(bn1(G1[b]))@W2^T) + b2 --
// smem u32: Ah[2304] | Al | Ph[2304] | Pl | W2h[1152] | W2l | Zth(u16 32*72) | Ztl
__global__ __launch_bounds__(128)
void k_fg2(const float* __restrict__ g1, const float* __restrict__ be1,
           const float* __restrict__ b2) {
    extern __shared__ unsigned sm[];
    unsigned* Ah = sm;
    unsigned* Al = sm + 2304;
    unsigned* Ph = sm + 4608;
    unsigned* Pl = sm + 6912;
    unsigned* W2h = sm + 9216;
    unsigned* W2l = sm + 10368;
    __nv_bfloat16* Zth = (__nv_bfloat16*)(sm + 11520);
    __nv_bfloat16* Ztl = (__nv_bfloat16*)(sm + 12672);
    __shared__ float a1s[64], c1s[64];

    int b = blockIdx.x, t = threadIdx.x;
    int wid = t >> 5, lane = t & 31, g = lane >> 2, c = lane & 3;
    int r = wid * 16 + g;

    if (t < 64) {
        const float invn = 1.0f / (float)(B_ * C1);
        float m = g_sum1[t] * invn;
        float v = g_ssq1[t] * invn - m * m;
        float aa = g1[t] * rsqrtf(v + 1e-5f);
        a1s[t] = aa;
        c1s[t] = be1[t] - m * aa;
    }
    for (int i = t; i < 64 * 32; i += 128) {
        int d = i >> 5, sp = i & 31;
        Ph[d * 36 + sp] = g_Ph[i]; Pl[d * 36 + sp] = g_Pl[i];
    }
    for (int i = t; i < 32 * 32; i += 128) {
        int n = i >> 5, kp = i & 31;
        W2h[n * 36 + kp] = g_W2h[i]; W2l[n * 36 + kp] = g_W2l[i];
    }
    __syncthreads();

    const float* Gb = g_G1 + (size_t)b * (NNODE * C1);
    for (int i = t; i < 64 * 32; i += 128) {
        int rr = i >> 5, kp = i & 31;
        float aa = a1s[rr], cc = c1s[rr];
        float v0 = fmaxf(fmaf(Gb[rr * 64 + 2 * kp], aa, cc), 0.f);
        float v1 = fmaxf(fmaf(Gb[rr * 64 + 2 * kp + 1], aa, cc), 0.f);
        uint2 s = split2(v0, v1);
        Ah[rr * 36 + kp] = s.x; Al[rr * 36 + kp] = s.y;
    }
    __syncthreads();

    // phase 1: Z = relu(bn(G1)) @ W2^T  (M=64 d, N=32 j, K=64)
    float acc[4][4] = {};
    #pragma unroll
    for (int kc = 0; kc < 4; kc++) {
        int ko = kc * 8;
        unsigned ah[4], al[4];
        ah[0] = Ah[r * 36 + c + ko];       ah[1] = Ah[(r + 8) * 36 + c + ko];
        ah[2] = Ah[r * 36 + c + 4 + ko];   ah[3] = Ah[(r + 8) * 36 + c + 4 + ko];
        al[0] = Al[r * 36 + c + ko];       al[1] = Al[(r + 8) * 36 + c + ko];
        al[2] = Al[r * 36 + c + 4 + ko];   al[3] = Al[(r + 8) * 36 + c + 4 + ko];
        #pragma unroll
        for (int ni = 0; ni < 4; ni++) {
            int n = ni * 8 + g;
            unsigned bh[2] = { W2h[n * 36 + c + ko], W2h[n * 36 + c + 4 + ko] };
            unsigned bl[2] = { W2l[n * 36 + c + ko], W2l[n * 36 + c + 4 + ko] };
            MMA_BF16(acc[ni], ah, bh);
            MMA_BF16(acc[ni], ah, bl);
            MMA_BF16(acc[ni], al, bh);
        }
    }

    // store Z transposed (bf16 split): Zt[j][s]
    #pragma unroll
    for (int ni = 0; ni < 4; ni++) {
        int cn = ni * 8 + 2 * c;
        __nv_bfloat16 h, l;
        bsplit(acc[ni][0], h, l); Zth[cn * 72 + r] = h;           Ztl[cn * 72 + r] = l;
        bsplit(acc[ni][1], h, l); Zth[(cn + 1) * 72 + r] = h;     Ztl[(cn + 1) * 72 + r] = l;
        bsplit(acc[ni][2], h, l); Zth[cn * 72 + r + 8] = h;       Ztl[cn * 72 + r + 8] = l;
        bsplit(acc[ni][3], h, l); Zth[(cn + 1) * 72 + r + 8] = h; Ztl[(cn + 1) * 72 + r + 8] = l;
    }
    __syncthreads();

    // phase 2: G2 = P @ Z + b2  (M=64 d, N=32 j, K=64 s)
    float ac2[4][4] = {};
    #pragma unroll
    for (int kc = 0; kc < 4; kc++) {
        int ko = kc * 8;
        unsigned ah[4], al[4];
        ah[0] = Ph[r * 36 + c + ko];       ah[1] = Ph[(r + 8) * 36 + c + ko];
        ah[2] = Ph[r * 36 + c + 4 + ko];   ah[3] = Ph[(r + 8) * 36 + c + 4 + ko];
        al[0] = Pl[r * 36 + c + ko];       al[1] = Pl[(r + 8) * 36 + c + ko];
        al[2] = Pl[r * 36 + c + 4 + ko];   al[3] = Pl[(r + 8) * 36 + c + 4 + ko];
        #pragma unroll
        for (int ni = 0; ni < 4; ni++) {
            int n = ni * 8 + g;
            unsigned bh[2], bl[2];
            bh[0] = *reinterpret_cast<const unsigned*>(&Zth[n * 72 + 2 * c + kc * 16]);
            bh[1] = *reinterpret_cast<const unsigned*>(&Zth[n * 72 + 2 * c + 8 + kc * 16]);
            bl[0] = *reinterpret_cast<const unsigned*>(&Ztl[n * 72 + 2 * c + kc * 16]);
            bl[1] = *reinterpret_cast<const unsigned*>(&Ztl[n * 72 + 2 * c + 8 + kc * 16]);
            MMA_BF16(ac2[ni], ah, bh);
            MMA_BF16(ac2[ni], ah, bl);
            MMA_BF16(ac2[ni], al, bh);
        }
    }

    // epilogue: + b2, write G2, BN2 stats
    float* out = g_G2 + (size_t)b * (NNODE * C2);
    float s0 = 0.f, q0 = 0.f, s1 = 0.f, q1 = 0.f;
    #pragma unroll
    for (int ni = 0; ni < 4; ni++) {
        int cn = ni * 8 + 2 * c;
        float bv0 = __ldg(&b2[cn]), bv1 = __ldg(&b2[cn + 1]);
        float v00 = ac2[ni][0] + bv0, v01 = ac2[ni][1] + bv1;
        float v10 = ac2[ni][2] + bv0, v11 = ac2[ni][3] + bv1;
        *reinterpret_cast<float2*>(&out[r * 32 + cn]) = make_float2(v00, v01);
        *reinterpret_cast<float2*>(&out[(r + 8) * 32 + cn]) = make_float2(v10, v11);
        s0 += v00 + v01; q0 += fmaf(v00, v00, v01 * v01);
        s1 += v10 + v11; q1 += fmaf(v10, v10, v11 * v11);
    }
    s0 += __shfl_xor_sync(0xffffffffu, s0, 1); s0 += __shfl_xor_sync(0xffffffffu, s0, 2);
    q0 += __shfl_xor_sync(0xffffffffu, q0, 1); q0 += __shfl_xor_sync(0xffffffffu, q0, 2);
    s1 += __shfl_xor_sync(0xffffffffu, s1, 1); s1 += __shfl_xor_sync(0xffffffffu, s1, 2);
    q1 += __shfl_xor_sync(0xffffffffu, q1, 1); q1 += __shfl_xor_sync(0xffffffffu, q1, 2);
    if (c == 0) {
        atomicAdd(&g_sum2[r], s0);     atomicAdd(&g_ssq2[r], q0);
        atomicAdd(&g_sum2[r + 8], s1); atomicAdd(&g_ssq2[r + 8], q1);
    }
}

// ---------------- K5: bn2 (inline coeffs) + relu + max-pool over nodes ---------------
__global__ void k_pool(const float* __restrict__ g2, const float* __restrict__ be2) {
    __shared__ float a2s[64], c2s[64];
    int t = threadIdx.x;
    if (t < 64) {
        const float invn = 1.0f / (float)(B_ * C2);
        float m = g_sum2[t] * invn;
        float v = g_ssq2[t] * invn - m * m;
        float aa = g2[t] * rsqrtf(v + 1e-5f);
        a2s[t] = aa;
        c2s[t] = be2[t] - m * aa;
    }
    __syncthreads();
    int bl = t >> 5, j = t & 31;
    int b = blockIdx.x * 8 + bl;
    const float* src = g_G2 + (size_t)b * 2048 + j;
    float m = 0.f;
    #pragma unroll 8
    for (int d = 0; d < 64; d++) {
        float v = fmaxf(fmaf(src[d * 32], a2s[d], c2s[d]), 0.f);
        m = fmaxf(m, v);
    }
    g_pool[b * 32 + j] = m;
}

// ---------------- MLP1 tensor-core (cp.async double-buffered): -----------------------
// H1 = relu(xf @ Wl1^T + bl1), bf16 split. smem ring: 2 stages.
// u32 layout: Ah[2][2560] @0 | Al[2][2560] @5120 | Bh[2][1280] @10240 | Bl[2][1280] @12800
__global__ __launch_bounds__(256, 2)
void k_mlp1_tc(const float* __restrict__ bias) {
    extern __shared__ unsigned smu[];
    unsigned sbase = (unsigned)__cvta_generic_to_shared(smu);
    int t = threadIdx.x;
    int m0 = blockIdx.x * 128, n0 = blockIdx.y * 64;
    int wid = t >> 5, lane = t & 31;
    int wm = (wid & 3) * 32, wn = (wid >> 2) * 32;
    int g = lane >> 2, c = lane & 3;
    int arow = t >> 2, ac4 = (t & 3) * 4;

    float acc[2][4][4] = {};

    // prefetch helper offsets (u32 indices)
    //   A stage s: s*2560 (Ah), 5120 + s*2560 (Al)
    //   B stage s: 10240 + s*1280 (Bh), 12800 + s*1280 (Bl)
    #define PREFETCH(ch, st) do {                                                   \
        int kb = (ch) * 16;                                                         \
        _Pragma("unroll")                                                           \
        for (int rep = 0; rep < 2; rep++) {                                         \
            int row = arow + rep * 64;                                              \
            size_t gi = (size_t)(m0 + row) * 1024 + kb + ac4;                       \
            cpa16(sbase + ((st) * 2560 + row * 20 + ac4) * 4, &g_Ah[gi]);           \
            cpa16(sbase + (5120 + (st) * 2560 + row * 20 + ac4) * 4, &g_Al[gi]);    \
        }                                                                           \
        {                                                                           \
            size_t gi = (size_t)(n0 + arow) * 1024 + kb + ac4;                      \
            cpa16(sbase + (10240 + (st) * 1280 + arow * 20 + ac4) * 4, &g_Bh[gi]);  \
            cpa16(sbase + (12800 + (st) * 1280 + arow * 20 + ac4) * 4, &g_Bl[gi]);  \
        }                                                                           \
        asm volatile("cp.async.commit_group;" ::: "memory");                        \
    } while (0)

    PREFETCH(0, 0);

    for (int ch = 0; ch < 64; ch++) {
        int st = ch & 1;
        if (ch < 63) {
            PREFETCH(ch + 1, st ^ 1);
            asm volatile("cp.async.wait_group 1;" ::: "memory");
        } else {
            asm volatile("cp.async.wait_group 0;" ::: "memory");
        }
        __syncthreads();

        const unsigned* Ah = smu + st * 2560;
        const unsigned* Al = smu + 5120 + st * 2560;
        const unsigned* Bh = smu + 10240 + st * 1280;
        const unsigned* Bl = smu + 12800 + st * 1280;

        #pragma unroll
        for (int kk = 0; kk < 2; kk++) {
            int ko = kk * 8;
            unsigned ah[2][4], al[2][4], bh[4][2], bl[4][2];
            #pragma unroll
            for (int mi = 0; mi < 2; mi++) {
                int r = wm + mi * 16 + g;
                ah[mi][0] = Ah[r * 20 + c + ko];
                ah[mi][1] = Ah[(r + 8) * 20 + c + ko];
                ah[mi][2] = Ah[r * 20 + c + 4 + ko];
                ah[mi][3] = Ah[(r + 8) * 20 + c + 4 + ko];
                al[mi][0] = Al[r * 20 + c + ko];
                al[mi][1] = Al[(r + 8) * 20 + c + ko];
                al[mi][2] = Al[r * 20 + c + 4 + ko];
                al[mi][3] = Al[(r + 8) * 20 + c + 4 + ko];
            }
            #pragma unroll
            for (int ni = 0; ni < 4; ni++) {
                int n = wn + ni * 8 + g;
                bh[ni][0] = Bh[n * 20 + c + ko];
                bh[ni][1] = Bh[n * 20 + c + 4 + ko];
                bl[ni][0] = Bl[n * 20 + c + ko];
                bl[ni][1] = Bl[n * 20 + c + 4 + ko];
            }
            #pragma unroll
            for (int mi = 0; mi < 2; mi++) {
                #pragma unroll
                for (int ni = 0; ni < 4; ni++) {
                    MMA_BF16(acc[mi][ni], ah[mi], bh[ni]);
                    MMA_BF16(acc[mi][ni], ah[mi], bl[ni]);
                    MMA_BF16(acc[mi][ni], al[mi], bh[ni]);
                }
            }
        }
        __syncthreads();
    }
    #undef PREFETCH

    #pragma unroll
    for (int mi = 0; mi < 2; mi++) {
        #pragma unroll
        for (int ni = 0; ni < 4; ni++) {
            int col = n0 + wn + ni * 8 + 2 * c;
            if (col < H1D) {
                float bv0 = __ldg(&bias[col]), bv1 = __ldg(&bias[col + 1]);
                int r0 = m0 + wm + mi * 16 + g;
                float* p0 = g_H1 + (size_t)r0 * H1D + col;
                float* p1 = g_H1 + (size_t)(r0 + 8) * H1D + col;
                p0[0] = fmaxf(acc[mi][ni][0] + bv0, 0.f);
                p0[1] = fmaxf(acc[mi][ni][1] + bv1, 0.f);
                p1[0] = fmaxf(acc[mi][ni][2] + bv0, 0.f);
                p1[1] = fmaxf(acc[mi][ni][3] + bv1, 0.f);
            }
        }
    }
}

// ---------------- MLP2 (scalar 64x64): H2 = relu(H1 @ Wl2^T + bl2) ----------------
__global__ void k_mlp2(const float* __restrict__ Bw, const float* __restrict__ bias) {
    __shared__ __align__(16) float As[16 * 68];
    __shared__ __align__(16) float Bs[16 * 68];
    const float* A = g_H1;
    float* C = g_H2;
    int m0 = blockIdx.x * 64;
    int t = threadIdx.x;
    int tm = (t >> 4) * 4, tn = (t & 15) * 4;
    float acc[4][4] = {};
    for (int k0 = 0; k0 < H1D; k0 += 16) {
        for (int i = t; i < 1024; i += 256) {
            int r = i >> 4, kk = i & 15;
            As[kk * 68 + r] = A[(size_t)(m0 + r) * H1D + k0 + kk];
            Bs[kk * 68 + r] = Bw[(size_t)r * H1D + k0 + kk];
        }
        __syncthreads();
        #pragma unroll
        for (int kk = 0; kk < 16; kk++) {
            float4 a = *reinterpret_cast<const float4*>(&As[kk * 68 + tm]);
            float4 b = *reinterpret_cast<const float4*>(&Bs[kk * 68 + tn]);
            acc[0][0] = fmaf(a.x, b.x, acc[0][0]); acc[0][1] = fmaf(a.x, b.y, acc[0][1]);
            acc[0][2] = fmaf(a.x, b.z, acc[0][2]); acc[0][3] = fmaf(a.x, b.w, acc[0][3]);
            acc[1][0] = fmaf(a.y, b.x, acc[1][0]); acc[1][1] = fmaf(a.y, b.y, acc[1][1]);
            acc[1][2] = fmaf(a.y, b.z, acc[1][2]); acc[1][3] = fmaf(a.y, b.w, acc[1][3]);
            acc[2][0] = fmaf(a.z, b.x, acc[2][0]); acc[2][1] = fmaf(a.z, b.y, acc[2][1]);
            acc[2][2] = fmaf(a.z, b.z, acc[2][2]); acc[2][3] = fmaf(a.z, b.w, acc[2][3]);
            acc[3][0] = fmaf(a.w, b.x, acc[3][0]); acc[3][1] = fmaf(a.w, b.y, acc[3][1]);
            acc[3][2] = fmaf(a.w, b.z, acc[3][2]); acc[3][3] = fmaf(a.w, b.w, acc[3][3]);
        }
        __syncthreads();
    }
    #pragma unroll
    for (int i = 0; i < 4; i++) {
        int row = m0 + tm + i;
        #pragma unroll
        for (int j = 0; j < 4; j++) {
            int col = tn + j;
            C[(size_t)row * H2D + col] = fmaxf(acc[i][j] + __ldg(&bias[col]), 0.f);
        }
    }
}

// ---------------- final: out = [pool, H2] @ Wfc^T + bfc ----------------
__global__ void k_final(const float* __restrict__ Wfc, const float* __restrict__ bfc,
                        float* __restrict__ out) {
    __shared__ float Ws[192];
    int t = threadIdx.x;
    if (t < 192) Ws[t] = Wfc[t];
    __syncthreads();
    int b = blockIdx.x * 256 + t;
    float a0 = __ldg(&bfc[0]), a1 = __ldg(&bfc[1]);
    const float* pp = g_pool + b * 32;
    const float* hh = g_H2 + b * 64;
    #pragma unroll
    for (int j = 0; j < 32; j++) {
        float v = pp[j];
        a0 = fmaf(v, Ws[j], a0);
        a1 = fmaf(v, Ws[96 + j], a1);
    }
    #pragma unroll
    for (int j = 0; j < 64; j++) {
        float v = hh[j];
        a0 = fmaf(v, Ws[32 + j], a0);
        a1 = fmaf(v, Ws[128 + j], a1);
    }
    out[b * 2]     = a0;
    out[b * 2 + 1] = a1;
}

// ---------------- launch ----------------
extern "C" void kernel_launch(void* const* d_in, const int* in_sizes, int n_in,
                              void* d_out, int out_size) {
    const float* xf  = (const float*)d_in[0];
    const float* xn  = (const float*)d_in[1];
    const int*   el  = (const int*)  d_in[2];
    const float* W1  = (const float*)d_in[3];
    const float* b1  = (const float*)d_in[4];
    const float* g1  = (const float*)d_in[5];
    const float* be1 = (const float*)d_in[6];
    const float* W2  = (const float*)d_in[7];
    const float* b2  = (const float*)d_in[8];
    const float* g2  = (const float*)d_in[9];
    const float* be2 = (const float*)d_in[10];
    const float* Wl1 = (const float*)d_in[11];
    const float* bl1 = (const float*)d_in[12];
    const float* Wl2 = (const float*)d_in[13];
    const float* bl2 = (const float*)d_in[14];
    const float* Wfc = (const float*)d_in[15];
    const float* bfc = (const float*)d_in[16];
    float* out = (float*)d_out;

    const int SMEM_FG1 = 15872 * 4;   // 63488 B
    const int SMEM_FG2 = 13824 * 4;   // 55296 B
    const int SMEM_MLP1 = 15360 * 4;  // 61440 B (2-stage ring)
    cudaFuncSetAttribute(k_fg1, cudaFuncAttributeMaxDynamicSharedMemorySize, SMEM_FG1);
    cudaFuncSetAttribute(k_fg2, cudaFuncAttributeMaxDynamicSharedMemorySize, SMEM_FG2);
    cudaFuncSetAttribute(k_mlp1_tc, cudaFuncAttributeMaxDynamicSharedMemorySize, SMEM_MLP1);

    k_prep<<<1, 256>>>(el, W1, W2);
    k_pack_b<<<(H1PAD * (DFP / 2)) / 256, 256>>>(Wl1);
    k_pack_a<<<(B_ * (DFP / 2)) / 256, 256>>>(xf);

    // graph path: fused tensor-core GCN layers
    k_fg1<<<B_, 128, SMEM_FG1>>>(xn, b1);
    k_fg2<<<B_, 128, SMEM_FG2>>>(g1, be1, b2);
    k_pool<<<B_ / 8, 256>>>(g2, be2);

    // fingerprint MLP path
    k_mlp1_tc<<<dim3(B_ / 128, H1PAD / 64), 256, SMEM_MLP1>>>(bl1);
    k_mlp2<<<B_ / 64, 256>>>(Wl2, bl2);

    k_final<<<B_ / 256, 256>>>(Wfc, bfc, out);
}

// round 16
// speedup vs baseline: 2.0390x; 1.3714x over previous
#include <cuda_runtime.h>
#include <cuda_bf16.h>

#define B_    4096
#define NNODE 64
#define FIN   67
#define C1    64
#define C2    32
#define DFP   2048
#define H1D   400
#define H1PAD 448
#define H2D   64
#define NEDGE 512

// ---------------- scratch (device globals; no allocations allowed) ----------------
__device__ float g_P [NNODE * NNODE];
__device__ float g_G1[B_ * NNODE * C1];
__device__ float g_G2[B_ * NNODE * C2];
__device__ float g_pool[B_ * C2];
__device__ float g_H1[B_ * H1D];
__device__ float g_H2[B_ * H2D];
__device__ float g_sum1[NNODE], g_ssq1[NNODE], g_sum2[NNODE], g_ssq2[NNODE];
// bf16-split packed operands (u32 = 2 bf16 along k)
__device__ unsigned g_Ah[B_ * (DFP / 2)];
__device__ unsigned g_Al[B_ * (DFP / 2)];
__device__ unsigned g_Bh[H1PAD * (DFP / 2)];
__device__ unsigned g_Bl[H1PAD * (DFP / 2)];
__device__ unsigned g_W1h[64 * 40], g_W1l[64 * 40];   // W1 [64][K80 pad] packed
__device__ unsigned g_Ph [64 * 32], g_Pl [64 * 32];   // P  [64][K64]     packed
__device__ unsigned g_W2h[32 * 32], g_W2l[32 * 32];   // W2 [32][K64]     packed

// ---------------- helpers ----------------
__device__ __forceinline__ uint2 split2(float x, float y) {
    __nv_bfloat16 hx = __float2bfloat16_rn(x), hy = __float2bfloat16_rn(y);
    float rx = x - __bfloat162float(hx), ry = y - __bfloat162float(hy);
    __nv_bfloat16 lx = __float2bfloat16_rn(rx), ly = __float2bfloat16_rn(ry);
    unsigned hi = ((unsigned)__bfloat16_as_ushort(hy) << 16) | __bfloat16_as_ushort(hx);
    unsigned lo = ((unsigned)__bfloat16_as_ushort(ly) << 16) | __bfloat16_as_ushort(lx);
    return make_uint2(hi, lo);
}
__device__ __forceinline__ void bsplit(float v, __nv_bfloat16& h, __nv_bfloat16& l) {
    h = __float2bfloat16_rn(v);
    l = __float2bfloat16_rn(v - __bfloat162float(h));
}
__device__ __forceinline__ void cpa16(unsigned saddr, const void* g) {
    asm volatile("cp.async.cg.shared.global [%0], [%1], 16;" :: "r"(saddr), "l"(g));
}

#define MMA_BF16(d, a, b) \
    asm volatile("mma.sync.aligned.m16n8k16.row.col.f32.bf16.bf16.f32 " \
        "{%0,%1,%2,%3},{%4,%5,%6,%7},{%8,%9},{%0,%1,%2,%3};\n" \
        : "+f"(d[0]), "+f"(d[1]), "+f"(d[2]), "+f"(d[3]) \
        : "r"(a[0]), "r"(a[1]), "r"(a[2]), "r"(a[3]), "r"(b[0]), "r"(b[1]))

// ---------------- K0: build P, pack P/W1/W2 to bf16 hi/lo, zero stats ----------------
__global__ void k_prep(const int* __restrict__ el, const float* __restrict__ W1,
                       const float* __restrict__ W2) {
    __shared__ float deg[NNODE];
    __shared__ float dinv[NNODE];
    __shared__ float Ps[NNODE * NNODE];
    int t = threadIdx.x;
    for (int i = t; i < 64 * 40; i += 256) {
        int n = i / 40, kp = i - n * 40;
        int k0 = 2 * kp;
        float v0 = (k0 < FIN) ? W1[n * FIN + k0] : 0.f;
        float v1 = (k0 + 1 < FIN) ? W1[n * FIN + k0 + 1] : 0.f;
        uint2 s = split2(v0, v1);
        g_W1h[i] = s.x; g_W1l[i] = s.y;
    }
    for (int i = t; i < 32 * 32; i += 256) {
        int n = i >> 5, kp = i & 31;
        uint2 s = split2(W2[n * 64 + 2 * kp], W2[n * 64 + 2 * kp + 1]);
        g_W2h[i] = s.x; g_W2l[i] = s.y;
    }
    if (t < NNODE) deg[t] = 0.f;
    for (int i = t; i < NNODE * NNODE; i += 256) Ps[i] = 0.f;
    __syncthreads();
    for (int i = t; i < NEDGE + NNODE; i += 256) {
        int d = (i < NEDGE) ? el[NEDGE + i] : (i - NEDGE);
        atomicAdd(&deg[d], 1.f);
    }
    __syncthreads();
    if (t < NNODE) dinv[t] = (deg[t] > 0.f) ? rsqrtf(deg[t]) : 0.f;
    __syncthreads();
    for (int i = t; i < NEDGE + NNODE; i += 256) {
        int s = (i < NEDGE) ? el[i] : (i - NEDGE);
        int d = (i < NEDGE) ? el[NEDGE + i] : (i - NEDGE);
        atomicAdd(&Ps[d * NNODE + s], dinv[s] * dinv[d]);
    }
    __syncthreads();
    for (int i = t; i < NNODE * NNODE; i += 256) g_P[i] = Ps[i];
    for (int i = t; i < 64 * 32; i += 256) {
        int d = i >> 5, sp = i & 31;
        uint2 s = split2(Ps[d * 64 + 2 * sp], Ps[d * 64 + 2 * sp + 1]);
        g_Ph[i] = s.x; g_Pl[i] = s.y;
    }
    if (t < NNODE) { g_sum1[t] = 0.f; g_ssq1[t] = 0.f; g_sum2[t] = 0.f; g_ssq2[t] = 0.f; }
}

// ---------------- pack kernels ----------------
__global__ void k_pack_a(const float* __restrict__ xf) {
    int idx = blockIdx.x * 256 + threadIdx.x;
    int row = idx >> 10, kc = idx & 1023;
    float2 v = *reinterpret_cast<const float2*>(&xf[(size_t)row * DFP + kc * 2]);
    uint2 s = split2(v.x, v.y);
    g_Ah[idx] = s.x; g_Al[idx] = s.y;
}
__global__ void k_pack_b(const float* __restrict__ Wl1) {
    int idx = blockIdx.x * 256 + threadIdx.x;
    int n = idx >> 10, kc = idx & 1023;
    float2 v = make_float2(0.f, 0.f);
    if (n < H1D) v = *reinterpret_cast<const float2*>(&Wl1[(size_t)n * DFP + kc * 2]);
    uint2 s = split2(v.x, v.y);
    g_Bh[idx] = s.x; g_Bl[idx] = s.y;
}

// ---------------- fused GCN1 (tensor core, low-smem): -------------------------------
// G1[b] = P @ (X[b]@W1^T) + b1, + BN1 stats.
// smem: 22.5KB static. Phase 1: W1 staged (stride 44), X split in registers.
// After sync the buffer is reused for the Y^T exchange. P fragments direct-LDG.
__global__ __launch_bounds__(128, 7)
void k_fg1(const float* __restrict__ xn, const float* __restrict__ b1) {
    __shared__ unsigned buf[5632];     // W1h[64*44] | W1l[64*44]; later Yth/Ytl
    int b = blockIdx.x, t = threadIdx.x;
    int wid = t >> 5, lane = t & 31, g = lane >> 2, c = lane & 3;
    int r = wid * 16 + g;

    for (int i = t; i < 64 * 40; i += 128) {
        int n = i / 40, kp = i - n * 40;
        buf[n * 44 + kp] = g_W1h[i];
        buf[2816 + n * 44 + kp] = g_W1l[i];
    }
    __syncthreads();

    const float* Xb = xn + (size_t)b * (NNODE * FIN);

    // phase 1: Y = X @ W1^T  (M=64, N=64, K=80); X fragments split in registers
    #define LDX(row, j, H, L) do {                                   \
        int kk_ = 2 * (j);                                           \
        float v0_ = (kk_ < FIN) ? Xb[(row) * FIN + kk_] : 0.f;       \
        float v1_ = (kk_ + 1 < FIN) ? Xb[(row) * FIN + kk_ + 1] : 0.f; \
        uint2 s_ = split2(v0_, v1_); (H) = s_.x; (L) = s_.y;         \
    } while (0)

    float acc[8][4] = {};
    #pragma unroll
    for (int kc = 0; kc < 5; kc++) {
        int ko = kc * 8;
        int j0 = c + ko, j1 = c + 4 + ko;
        unsigned ah[4], al[4];
        LDX(r,     j0, ah[0], al[0]);
        LDX(r + 8, j0, ah[1], al[1]);
        LDX(r,     j1, ah[2], al[2]);
        LDX(r + 8, j1, ah[3], al[3]);
        #pragma unroll
        for (int ni = 0; ni < 8; ni++) {
            int n = ni * 8 + g;
            unsigned bh[2] = { buf[n * 44 + j0], buf[n * 44 + j1] };
            unsigned bl[2] = { buf[2816 + n * 44 + j0], buf[2816 + n * 44 + j1] };
            MMA_BF16(acc[ni], ah, bh);
            MMA_BF16(acc[ni], ah, bl);
            MMA_BF16(acc[ni], al, bh);
        }
    }
    #undef LDX
    __syncthreads();   // all W1 reads done; buffer is reusable

    // store Y transposed (bf16 split) into the same buffer: Yt[o][s], stride 72
    __nv_bfloat16* Yth = (__nv_bfloat16*)buf;             // 64*72 u16 = 2304 u32
    __nv_bfloat16* Ytl = (__nv_bfloat16*)(buf + 2304);
    #pragma unroll
    for (int ni = 0; ni < 8; ni++) {
        int cn = ni * 8 + 2 * c;
        __nv_bfloat16 h, l;
        bsplit(acc[ni][0], h, l); Yth[cn * 72 + r] = h;           Ytl[cn * 72 + r] = l;
        bsplit(acc[ni][1], h, l); Yth[(cn + 1) * 72 + r] = h;     Ytl[(cn + 1) * 72 + r] = l;
        bsplit(acc[ni][2], h, l); Yth[cn * 72 + r + 8] = h;       Ytl[cn * 72 + r + 8] = l;
        bsplit(acc[ni][3], h, l); Yth[(cn + 1) * 72 + r + 8] = h; Ytl[(cn + 1) * 72 + r + 8] = l;
    }
    __syncthreads();

    // phase 2: G1 = P @ Y + b1  (P fragments direct from global, L1-hot)
    float ac2[8][4] = {};
    #pragma unroll
    for (int kc = 0; kc < 4; kc++) {
        int ko = kc * 8;
        int j0 = c + ko, j1 = c + 4 + ko;
        unsigned ah[4], al[4];
        ah[0] = g_Ph[r * 32 + j0];       ah[1] = g_Ph[(r + 8) * 32 + j0];
        ah[2] = g_Ph[r * 32 + j1];       ah[3] = g_Ph[(r + 8) * 32 + j1];
        al[0] = g_Pl[r * 32 + j0];       al[1] = g_Pl[(r + 8) * 32 + j0];
        al[2] = g_Pl[r * 32 + j1];       al[3] = g_Pl[(r + 8) * 32 + j1];
        #pragma unroll
        for (int ni = 0; ni < 8; ni++) {
            int n = ni * 8 + g;
            unsigned bh[2], bl[2];
            bh[0] = *reinterpret_cast<const unsigned*>(&Yth[n * 72 + 2 * c + kc * 16]);
            bh[1] = *reinterpret_cast<const unsigned*>(&Yth[n * 72 + 2 * c + 8 + kc * 16]);
            bl[0] = *reinterpret_cast<const unsigned*>(&Ytl[n * 72 + 2 * c + kc * 16]);
            bl[1] = *reinterpret_cast<const unsigned*>(&Ytl[n * 72 + 2 * c + 8 + kc * 16]);
            MMA_BF16(ac2[ni], ah, bh);
            MMA_BF16(ac2[ni], ah, bl);
            MMA_BF16(ac2[ni], al, bh);
        }
    }

    // epilogue: + b1, write G1, BN1 stats
    float* out = g_G1 + (size_t)b * (NNODE * C1);
    float s0 = 0.f, q0 = 0.f, s1 = 0.f, q1 = 0.f;
    #pragma unroll
    for (int ni = 0; ni < 8; ni++) {
        int cn = ni * 8 + 2 * c;
        float bv0 = __ldg(&b1[cn]), bv1 = __ldg(&b1[cn + 1]);
        float v00 = ac2[ni][0] + bv0, v01 = ac2[ni][1] + bv1;
        float v10 = ac2[ni][2] + bv0, v11 = ac2[ni][3] + bv1;
        *reinterpret_cast<float2*>(&out[r * 64 + cn]) = make_float2(v00, v01);
        *reinterpret_cast<float2*>(&out[(r + 8) * 64 + cn]) = make_float2(v10, v11);
        s0 += v00 + v01; q0 += fmaf(v00, v00, v01 * v01);
        s1 += v10 + v11; q1 += fmaf(v10, v10, v11 * v11);
    }
    s0 += __shfl_xor_sync(0xffffffffu, s0, 1); s0 += __shfl_xor_sync(0xffffffffu, s0, 2);
    q0 += __shfl_xor_sync(0xffffffffu, q0, 1); q0 += __shfl_xor_sync(0xffffffffu, q0, 2);
    s1 += __shfl_xor_sync(0xffffffffu, s1, 1); s1 += __shfl_xor_sync(0xffffffffu, s1, 2);
    q1 += __shfl_xor_sync(0xffffffffu, q1, 1); q1 += __shfl_xor_sync(0xffffffffu, q1, 2);
    if (c == 0) {
        atomicAdd(&g_sum1[r], s0);     atomicAdd(&g_ssq1[r], q0);
        atomicAdd(&g_sum1[r + 8], s1); atomicAdd(&g_ssq1[r + 8], q1);
    }
}

// ---------------- fused GCN2 (tensor core, low-smem): -------------------------------
// G2[b] = P @ (relu(bn1(G1[b]))@W2^T) + b2, + BN2 stats.
// smem: only Z^T exchange (9.2KB) + bn coeffs. A/W2/P fragments in registers / direct LDG.
__global__ __launch_bounds__(128, 8)
void k_fg2(const float* __restrict__ g1, const float* __restrict__ be1,
           const float* __restrict__ b2) {
    __shared__ __nv_bfloat16 Zth[32 * 72], Ztl[32 * 72];
    __shared__ float a1s[64], c1s[64];

    int b = blockIdx.x, t = threadIdx.x;
    int wid = t >> 5, lane = t & 31, g = lane >> 2, c = lane & 3;
    int r = wid * 16 + g;

    if (t < 64) {
        const float invn = 1.0f / (float)(B_ * C1);
        float m = g_sum1[t] * invn;
        float v = g_ssq1[t] * invn - m * m;
        float aa = g1[t] * rsqrtf(v + 1e-5f);
        a1s[t] = aa;
        c1s[t] = be1[t] - m * aa;
    }
    __syncthreads();

    const float* Gb = g_G1 + (size_t)b * (NNODE * C1);
    float aa0 = a1s[r], cc0 = c1s[r], aa1 = a1s[r + 8], cc1 = c1s[r + 8];

    // phase 1: Z = relu(bn(G1)) @ W2^T  (M=64 d, N=32 j, K=64)
    #define LDA(row, j, AA, CC, H, L) do {                                         \
        float2 v_ = *reinterpret_cast<const float2*>(&Gb[(row) * 64 + 2 * (j)]);   \
        float v0_ = fmaxf(fmaf(v_.x, (AA), (CC)), 0.f);                            \
        float v1_ = fmaxf(fmaf(v_.y, (AA), (CC)), 0.f);                            \
        uint2 s_ = split2(v0_, v1_); (H) = s_.x; (L) = s_.y;                       \
    } while (0)

    float acc[4][4] = {};
    #pragma unroll
    for (int kc = 0; kc < 4; kc++) {
        int ko = kc * 8;
        int j0 = c + ko, j1 = c + 4 + ko;
        unsigned ah[4], al[4];
        LDA(r,     j0, aa0, cc0, ah[0], al[0]);
        LDA(r + 8, j0, aa1, cc1, ah[1], al[1]);
        LDA(r,     j1, aa0, cc0, ah[2], al[2]);
        LDA(r + 8, j1, aa1, cc1, ah[3], al[3]);
        #pragma unroll
        for (int ni = 0; ni < 4; ni++) {
            int n = ni * 8 + g;
            unsigned bh[2] = { g_W2h[n * 32 + j0], g_W2h[n * 32 + j1] };
            unsigned bl[2] = { g_W2l[n * 32 + j0], g_W2l[n * 32 + j1] };
            MMA_BF16(acc[ni], ah, bh);
            MMA_BF16(acc[ni], ah, bl);
            MMA_BF16(acc[ni], al, bh);
        }
    }
    #undef LDA

    // store Z transposed (bf16 split): Zt[j][s]
    #pragma unroll
    for (int ni = 0; ni < 4; ni++) {
        int cn = ni * 8 + 2 * c;
        __nv_bfloat16 h, l;
        bsplit(acc[ni][0], h, l); Zth[cn * 72 + r] = h;           Ztl[cn * 72 + r] = l;
        bsplit(acc[ni][1], h, l); Zth[(cn + 1) * 72 + r] = h;     Ztl[(cn + 1) * 72 + r] = l;
        bsplit(acc[ni][2], h, l); Zth[cn * 72 + r + 8] = h;       Ztl[cn * 72 + r + 8] = l;
        bsplit(acc[ni][3], h, l); Zth[(cn + 1) * 72 + r + 8] = h; Ztl[(cn + 1) * 72 + r + 8] = l;
    }
    __syncthreads();

    // phase 2: G2 = P @ Z + b2  (P fragments direct from global)
    float ac2[4][4] = {};
    #pragma unroll
    for (int kc = 0; kc < 4; kc++) {
        int ko = kc * 8;
        int j0 = c + ko, j1 = c + 4 + ko;
        unsigned ah[4], al[4];
        ah[0] = g_Ph[r * 32 + j0];       ah[1] = g_Ph[(r + 8) * 32 + j0];
        ah[2] = g_Ph[r * 32 + j1];       ah[3] = g_Ph[(r + 8) * 32 + j1];
        al[0] = g_Pl[r * 32 + j0];       al[1] = g_Pl[(r + 8) * 32 + j0];
        al[2] = g_Pl[r * 32 + j1];       al[3] = g_Pl[(r + 8) * 32 + j1];
        #pragma unroll
        for (int ni = 0; ni < 4; ni++) {
            int n = ni * 8 + g;
            unsigned bh[2], bl[2];
            bh[0] = *reinterpret_cast<const unsigned*>(&Zth[n * 72 + 2 * c + kc * 16]);
            bh[1] = *reinterpret_cast<const unsigned*>(&Zth[n * 72 + 2 * c + 8 + kc * 16]);
            bl[0] = *reinterpret_cast<const unsigned*>(&Ztl[n * 72 + 2 * c + kc * 16]);
            bl[1] = *reinterpret_cast<const unsigned*>(&Ztl[n * 72 + 2 * c + 8 + kc * 16]);
            MMA_BF16(ac2[ni], ah, bh);
            MMA_BF16(ac2[ni], ah, bl);
            MMA_BF16(ac2[ni], al, bh);
        }
    }

    // epilogue: + b2, write G2, BN2 stats
    float* out = g_G2 + (size_t)b * (NNODE * C2);
    float s0 = 0.f, q0 = 0.f, s1 = 0.f, q1 = 0.f;
    #pragma unroll
    for (int ni = 0; ni < 4; ni++) {
        int cn = ni * 8 + 2 * c;
        float bv0 = __ldg(&b2[cn]), bv1 = __ldg(&b2[cn + 1]);
        float v00 = ac2[ni][0] + bv0, v01 = ac2[ni][1] + bv1;
        float v10 = ac2[ni][2] + bv0, v11 = ac2[ni][3] + bv1;
        *reinterpret_cast<float2*>(&out[r * 32 + cn]) = make_float2(v00, v01);
        *reinterpret_cast<float2*>(&out[(r + 8) * 32 + cn]) = make_float2(v10, v11);
        s0 += v00 + v01; q0 += fmaf(v00, v00, v01 * v01);
        s1 += v10 + v11; q1 += fmaf(v10, v10, v11 * v11);
    }
    s0 += __shfl_xor_sync(0xffffffffu, s0, 1); s0 += __shfl_xor_sync(0xffffffffu, s0, 2);
    q0 += __shfl_xor_sync(0xffffffffu, q0, 1); q0 += __shfl_xor_sync(0xffffffffu, q0, 2);
    s1 += __shfl_xor_sync(0xffffffffu, s1, 1); s1 += __shfl_xor_sync(0xffffffffu, s1, 2);
    q1 += __shfl_xor_sync(0xffffffffu, q1, 1); q1 += __shfl_xor_sync(0xffffffffu, q1, 2);
    if (c == 0) {
        atomicAdd(&g_sum2[r], s0);     atomicAdd(&g_ssq2[r], q0);
        atomicAdd(&g_sum2[r + 8], s1); atomicAdd(&g_ssq2[r + 8], q1);
    }
}

// ---------------- K5: bn2 (inline coeffs) + relu + max-pool over nodes ---------------
__global__ void k_pool(const float* __restrict__ g2, const float* __restrict__ be2) {
    __shared__ float a2s[64], c2s[64];
    int t = threadIdx.x;
    if (t < 64) {
        const float invn = 1.0f / (float)(B_ * C2);
        float m = g_sum2[t] * invn;
        float v = g_ssq2[t] * invn - m * m;
        float aa = g2[t] * rsqrtf(v + 1e-5f);
        a2s[t] = aa;
        c2s[t] = be2[t] - m * aa;
    }
    __syncthreads();
    int bl = t >> 5, j = t & 31;
    int b = blockIdx.x * 8 + bl;
    const float* src = g_G2 + (size_t)b * 2048 + j;
    float m = 0.f;
    #pragma unroll 8
    for (int d = 0; d < 64; d++) {
        float v = fmaxf(fmaf(src[d * 32], a2s[d], c2s[d]), 0.f);
        m = fmaxf(m, v);
    }
    g_pool[b * 32 + j] = m;
}

// ---------------- MLP1 tensor-core (cp.async double-buffered) ------------------------
__global__ __launch_bounds__(256, 2)
void k_mlp1_tc(const float* __restrict__ bias) {
    extern __shared__ unsigned smu[];
    unsigned sbase = (unsigned)__cvta_generic_to_shared(smu);
    int t = threadIdx.x;
    int m0 = blockIdx.x * 128, n0 = blockIdx.y * 64;
    int wid = t >> 5, lane = t & 31;
    int wm = (wid & 3) * 32, wn = (wid >> 2) * 32;
    int g = lane >> 2, c = lane & 3;
    int arow = t >> 2, ac4 = (t & 3) * 4;

    float acc[2][4][4] = {};

    #define PREFETCH(ch, st) do {                                                   \
        int kb = (ch) * 16;                                                         \
        _Pragma("unroll")                                                           \
        for (int rep = 0; rep < 2; rep++) {                                         \
            int row = arow + rep * 64;                                              \
            size_t gi = (size_t)(m0 + row) * 1024 + kb + ac4;                       \
            cpa16(sbase + ((st) * 2560 + row * 20 + ac4) * 4, &g_Ah[gi]);           \
            cpa16(sbase + (5120 + (st) * 2560 + row * 20 + ac4) * 4, &g_Al[gi]);    \
        }                                                                           \
        {                                                                           \
            size_t gi = (size_t)(n0 + arow) * 1024 + kb + ac4;                      \
            cpa16(sbase + (10240 + (st) * 1280 + arow * 20 + ac4) * 4, &g_Bh[gi]);  \
            cpa16(sbase + (12800 + (st) * 1280 + arow * 20 + ac4) * 4, &g_Bl[gi]);  \
        }                                                                           \
        asm volatile("cp.async.commit_group;" ::: "memory");                        \
    } while (0)

    PREFETCH(0, 0);

    for (int ch = 0; ch < 64; ch++) {
        int st = ch & 1;
        if (ch < 63) {
            PREFETCH(ch + 1, st ^ 1);
            asm volatile("cp.async.wait_group 1;" ::: "memory");
        } else {
            asm volatile("cp.async.wait_group 0;" ::: "memory");
        }
        __syncthreads();

        const unsigned* Ah = smu + st * 2560;
        const unsigned* Al = smu + 5120 + st * 2560;
        const unsigned* Bh = smu + 10240 + st * 1280;
        const unsigned* Bl = smu + 12800 + st * 1280;

        #pragma unroll
        for (int kk = 0; kk < 2; kk++) {
            int ko = kk * 8;
            unsigned ah[2][4], al[2][4], bh[4][2], bl[4][2];
            #pragma unroll
            for (int mi = 0; mi < 2; mi++) {
                int r = wm + mi * 16 + g;
                ah[mi][0] = Ah[r * 20 + c + ko];
                ah[mi][1] = Ah[(r + 8) * 20 + c + ko];
                ah[mi][2] = Ah[r * 20 + c + 4 + ko];
                ah[mi][3] = Ah[(r + 8) * 20 + c + 4 + ko];
                al[mi][0] = Al[r * 20 + c + ko];
                al[mi][1] = Al[(r + 8) * 20 + c + ko];
                al[mi][2] = Al[r * 20 + c + 4 + ko];
                al[mi][3] = Al[(r + 8) * 20 + c + 4 + ko];
            }
            #pragma unroll
            for (int ni = 0; ni < 4; ni++) {
                int n = wn + ni * 8 + g;
                bh[ni][0] = Bh[n * 20 + c + ko];
                bh[ni][1] = Bh[n * 20 + c + 4 + ko];
                bl[ni][0] = Bl[n * 20 + c + ko];
                bl[ni][1] = Bl[n * 20 + c + 4 + ko];
            }
            #pragma unroll
            for (int mi = 0; mi < 2; mi++) {
                #pragma unroll
                for (int ni = 0; ni < 4; ni++) {
                    MMA_BF16(acc[mi][ni], ah[mi], bh[ni]);
                    MMA_BF16(acc[mi][ni], ah[mi], bl[ni]);
                    MMA_BF16(acc[mi][ni], al[mi], bh[ni]);
                }
            }
        }
        __syncthreads();
    }
    #undef PREFETCH

    #pragma unroll
    for (int mi = 0; mi < 2; mi++) {
        #pragma unroll
        for (int ni = 0; ni < 4; ni++) {
            int col = n0 + wn + ni * 8 + 2 * c;
            if (col < H1D) {
                float bv0 = __ldg(&bias[col]), bv1 = __ldg(&bias[col + 1]);
                int r0 = m0 + wm + mi * 16 + g;
                float* p0 = g_H1 + (size_t)r0 * H1D + col;
                float* p1 = g_H1 + (size_t)(r0 + 8) * H1D + col;
                p0[0] = fmaxf(acc[mi][ni][0] + bv0, 0.f);
                p0[1] = fmaxf(acc[mi][ni][1] + bv1, 0.f);
                p1[0] = fmaxf(acc[mi][ni][2] + bv0, 0.f);
                p1[1] = fmaxf(acc[mi][ni][3] + bv1, 0.f);
            }
        }
    }
}

// ---------------- MLP2 (scalar 64x64): H2 = relu(H1 @ Wl2^T + bl2) ----------------
__global__ void k_mlp2(const float* __restrict__ Bw, const float* __restrict__ bias) {
    __shared__ __align__(16) float As[16 * 68];
    __shared__ __align__(16) float Bs[16 * 68];
    const float* A = g_H1;
    float* C = g_H2;
    int m0 = blockIdx.x * 64;
    int t = threadIdx.x;
    int tm = (t >> 4) * 4, tn = (t & 15) * 4;
    float acc[4][4] = {};
    for (int k0 = 0; k0 < H1D; k0 += 16) {
        for (int i = t; i < 1024; i += 256) {
            int r = i >> 4, kk = i & 15;
            As[kk * 68 + r] = A[(size_t)(m0 + r) * H1D + k0 + kk];
            Bs[kk * 68 + r] = Bw[(size_t)r * H1D + k0 + kk];
        }
        __syncthreads();
        #pragma unroll
        for (int kk = 0; kk < 16; kk++) {
            float4 a = *reinterpret_cast<const float4*>(&As[kk * 68 + tm]);
            float4 b = *reinterpret_cast<const float4*>(&Bs[kk * 68 + tn]);
            acc[0][0] = fmaf(a.x, b.x, acc[0][0]); acc[0][1] = fmaf(a.x, b.y, acc[0][1]);
            acc[0][2] = fmaf(a.x, b.z, acc[0][2]); acc[0][3] = fmaf(a.x, b.w, acc[0][3]);
            acc[1][0] = fmaf(a.y, b.x, acc[1][0]); acc[1][1] = fmaf(a.y, b.y, acc[1][1]);
            acc[1][2] = fmaf(a.y, b.z, acc[1][2]); acc[1][3] = fmaf(a.y, b.w, acc[1][3]);
            acc[2][0] = fmaf(a.z, b.x, acc[2][0]); acc[2][1] = fmaf(a.z, b.y, acc[2][1]);
            acc[2][2] = fmaf(a.z, b.z, acc[2][2]); acc[2][3] = fmaf(a.z, b.w, acc[2][3]);
            acc[3][0] = fmaf(a.w, b.x, acc[3][0]); acc[3][1] = fmaf(a.w, b.y, acc[3][1]);
            acc[3][2] = fmaf(a.w, b.z, acc[3][2]); acc[3][3] = fmaf(a.w, b.w, acc[3][3]);
        }
        __syncthreads();
    }
    #pragma unroll
    for (int i = 0; i < 4; i++) {
        int row = m0 + tm + i;
        #pragma unroll
        for (int j = 0; j < 4; j++) {
            int col = tn + j;
            C[(size_t)row * H2D + col] = fmaxf(acc[i][j] + __ldg(&bias[col]), 0.f);
        }
    }
}

// ---------------- final: out = [pool, H2] @ Wfc^T + bfc ----------------
__global__ void k_final(const float* __restrict__ Wfc, const float* __restrict__ bfc,
                        float* __restrict__ out) {
    __shared__ float Ws[192];
    int t = threadIdx.x;
    if (t < 192) Ws[t] = Wfc[t];
    __syncthreads();
    int b = blockIdx.x * 256 + t;
    float a0 = __ldg(&bfc[0]), a1 = __ldg(&bfc[1]);
    const float* pp = g_pool + b * 32;
    const float* hh = g_H2 + b * 64;
    #pragma unroll
    for (int j = 0; j < 32; j++) {
        float v = pp[j];
        a0 = fmaf(v, Ws[j], a0);
        a1 = fmaf(v, Ws[96 + j], a1);
    }
    #pragma unroll
    for (int j = 0; j < 64; j++) {
        float v = hh[j];
        a0 = fmaf(v, Ws[32 + j], a0);
        a1 = fmaf(v, Ws[128 + j], a1);
    }
    out[b * 2]     = a0;
    out[b * 2 + 1] = a1;
}

// ---------------- launch ----------------
extern "C" void kernel_launch(void* const* d_in, const int* in_sizes, int n_in,
                              void* d_out, int out_size) {
    const float* xf  = (const float*)d_in[0];
    const float* xn  = (const float*)d_in[1];
    const int*   el  = (const int*)  d_in[2];
    const float* W1  = (const float*)d_in[3];
    const float* b1  = (const float*)d_in[4];
    const float* g1  = (const float*)d_in[5];
    const float* be1 = (const float*)d_in[6];
    const float* W2  = (const float*)d_in[7];
    const float* b2  = (const float*)d_in[8];
    const float* g2  = (const float*)d_in[9];
    const float* be2 = (const float*)d_in[10];
    const float* Wl1 = (const float*)d_in[11];
    const float* bl1 = (const float*)d_in[12];
    const float* Wl2 = (const float*)d_in[13];
    const float* bl2 = (const float*)d_in[14];
    const float* Wfc = (const float*)d_in[15];
    const float* bfc = (const float*)d_in[16];
    float* out = (float*)d_out;

    const int SMEM_MLP1 = 15360 * 4;  // 61440 B (2-stage ring)
    cudaFuncSetAttribute(k_mlp1_tc, cudaFuncAttributeMaxDynamicSharedMemorySize, SMEM_MLP1);

    k_prep<<<1, 256>>>(el, W1, W2);
    k_pack_b<<<(H1PAD * (DFP / 2)) / 256, 256>>>(Wl1);
    k_pack_a<<<(B_ * (DFP / 2)) / 256, 256>>>(xf);

    // graph path: fused tensor-core GCN layers (low-smem, high-occupancy)
    k_fg1<<<B_, 128>>>(xn, b1);
    k_fg2<<<B_, 128>>>(g1, be1, b2);
    k_pool<<<B_ / 8, 256>>>(g2, be2);

    // fingerprint MLP path
    k_mlp1_tc<<<dim3(B_ / 128, H1PAD / 64), 256, SMEM_MLP1>>>(bl1);
    k_mlp2<<<B_ / 64, 256>>>(Wl2, bl2);

    k_final<<<B_ / 256, 256>>>(Wfc, bfc, out);
}